// round 1
// baseline (speedup 1.0000x reference)
#include <cuda_runtime.h>
#include <cstdint>

#define V_TOTAL 1497600
#define E_TOTAL 4492800
#define BATCH   256
#define VPM     5850
#define K2DIM   58500   /* VPM*10 */
#define NOUT    64
#define NEG     0.01f

// ---------------- scratch (static __device__, no allocations) ----------------
__device__ float4 g_sa[V_TOTAL];            // layer-a neighbor sums (xyz) + degree (w)
__device__ float  g_x1[V_TOTAL * 5];        // layer-a output (post-leaky)
__device__ float4 g_sb4[V_TOTAL];           // layer-b neighbor sums [0:4)
__device__ float  g_sb1[V_TOTAL];           // layer-b neighbor sums [4]
__device__ float  g_y[V_TOTAL * 10];        // fc1 output (post-leaky)
__device__ float  g_acc[BATCH * NOUT];      // fc2 split-K accumulator

// ---------------- vector reductions ----------------
__device__ __forceinline__ void red_add_v4(float4* addr, float a, float b, float c, float d) {
    asm volatile("red.global.add.v4.f32 [%0], {%1,%2,%3,%4};"
                 :: "l"(addr), "f"(a), "f"(b), "f"(c), "f"(d) : "memory");
}
__device__ __forceinline__ void red_add_f32(float* addr, float a) {
    asm volatile("red.global.add.f32 [%0], %1;" :: "l"(addr), "f"(a) : "memory");
}
__device__ __forceinline__ float leaky(float t) { return t >= 0.f ? t : NEG * t; }

// ---------------- K0: zero accumulators ----------------
__global__ void k_zero() {
    int i = blockIdx.x * blockDim.x + threadIdx.x;
    int stride = gridDim.x * blockDim.x;
    float4 z4 = make_float4(0.f, 0.f, 0.f, 0.f);
    for (int v = i; v < V_TOTAL; v += stride) {
        g_sa[v]  = z4;
        g_sb4[v] = z4;
        g_sb1[v] = 0.f;
    }
    if (i < BATCH * NOUT) g_acc[i] = 0.f;
}

// ---------------- K1: scatter raw verts + degree ----------------
__global__ void k_scatter_a(const float* __restrict__ verts, const int2* __restrict__ edges) {
    int e = blockIdx.x * blockDim.x + threadIdx.x;
    if (e >= E_TOTAL) return;
    int2 ij = edges[e];
    int i = ij.x, j = ij.y;
    float xi0 = __ldg(verts + 3 * i + 0);
    float xi1 = __ldg(verts + 3 * i + 1);
    float xi2 = __ldg(verts + 3 * i + 2);
    float xj0 = __ldg(verts + 3 * j + 0);
    float xj1 = __ldg(verts + 3 * j + 1);
    float xj2 = __ldg(verts + 3 * j + 2);
    red_add_v4(g_sa + i, xj0, xj1, xj2, 1.f);
    red_add_v4(g_sa + j, xi0, xi1, xi2, 1.f);
}

// ---------------- K2: x1 = leaky(verts@w0a^T + b0a + sa@w1a^T + deg*b1a) ----------------
__global__ void k_x1(const float* __restrict__ verts,
                     const float* __restrict__ w0a, const float* __restrict__ b0a,
                     const float* __restrict__ w1a, const float* __restrict__ b1a) {
    int v = blockIdx.x * blockDim.x + threadIdx.x;
    if (v >= V_TOTAL) return;
    float p0 = verts[3 * v + 0], p1 = verts[3 * v + 1], p2 = verts[3 * v + 2];
    float4 s = g_sa[v];
#pragma unroll
    for (int m = 0; m < 5; m++) {
        float t = __ldg(b0a + m) + s.w * __ldg(b1a + m);
        t += p0 * __ldg(w0a + 3 * m + 0) + p1 * __ldg(w0a + 3 * m + 1) + p2 * __ldg(w0a + 3 * m + 2);
        t += s.x * __ldg(w1a + 3 * m + 0) + s.y * __ldg(w1a + 3 * m + 1) + s.z * __ldg(w1a + 3 * m + 2);
        g_x1[5 * v + m] = leaky(t);
    }
}

// ---------------- K3: scatter x1 ----------------
__global__ void k_scatter_b(const int2* __restrict__ edges) {
    int e = blockIdx.x * blockDim.x + threadIdx.x;
    if (e >= E_TOTAL) return;
    int2 ij = edges[e];
    const float* xi = g_x1 + 5 * (long long)ij.x;
    const float* xj = g_x1 + 5 * (long long)ij.y;
    float a0 = __ldg(xi + 0), a1 = __ldg(xi + 1), a2 = __ldg(xi + 2), a3 = __ldg(xi + 3), a4 = __ldg(xi + 4);
    float b0 = __ldg(xj + 0), b1 = __ldg(xj + 1), b2 = __ldg(xj + 2), b3 = __ldg(xj + 3), b4 = __ldg(xj + 4);
    red_add_v4(g_sb4 + ij.x, b0, b1, b2, b3);
    red_add_f32(g_sb1 + ij.x, b4);
    red_add_v4(g_sb4 + ij.y, a0, a1, a2, a3);
    red_add_f32(g_sb1 + ij.y, a4);
}

// ---------------- K4: fused layer-b combine + fc1 (4 verts/thread) ----------------
__global__ __launch_bounds__(256)
void k_vertex(const float* __restrict__ w0b, const float* __restrict__ b0b,
              const float* __restrict__ w1b, const float* __restrict__ b1b,
              const float* __restrict__ fc1w, const float* __restrict__ fc1b) {
    __shared__ float s_w0b[100], s_w1b[100], s_b0b[20], s_b1b[20], s_f1[200], s_f1b[16];
    int tid = threadIdx.x;
    if (tid < 100) { s_w0b[tid] = w0b[tid]; s_w1b[tid] = w1b[tid]; }
    if (tid < 20)  { s_b0b[tid] = b0b[tid]; s_b1b[tid] = b1b[tid]; }
    if (tid < 200) s_f1[tid] = fc1w[tid];
    if (tid < 10)  s_f1b[tid] = fc1b[tid];
    __syncthreads();

    int base = (blockIdx.x * blockDim.x + threadIdx.x) * 4;
    if (base >= V_TOTAL) return;   // V_TOTAL % 4 == 0, so all 4 verts valid

    float x1[4][5], sb[4][5], deg[4], yacc[4][10];
#pragma unroll
    for (int u = 0; u < 4; u++) {
        int v = base + u;
#pragma unroll
        for (int m = 0; m < 5; m++) x1[u][m] = g_x1[5 * v + m];
        float4 s4 = g_sb4[v];
        sb[u][0] = s4.x; sb[u][1] = s4.y; sb[u][2] = s4.z; sb[u][3] = s4.w;
        sb[u][4] = g_sb1[v];
        deg[u] = g_sa[v].w;
#pragma unroll
        for (int q = 0; q < 10; q++) yacc[u][q] = s_f1b[q];
    }

#pragma unroll
    for (int n = 0; n < 20; n++) {
        float w0r[5], w1r[5];
#pragma unroll
        for (int m = 0; m < 5; m++) { w0r[m] = s_w0b[5 * n + m]; w1r[m] = s_w1b[5 * n + m]; }
        float bb0 = s_b0b[n], bb1 = s_b1b[n];
        float x2[4];
#pragma unroll
        for (int u = 0; u < 4; u++) {
            float t = bb0 + deg[u] * bb1;
#pragma unroll
            for (int m = 0; m < 5; m++) t += x1[u][m] * w0r[m] + sb[u][m] * w1r[m];
            x2[u] = leaky(t);
        }
#pragma unroll
        for (int q = 0; q < 10; q++) {
            float fw = s_f1[20 * q + n];
#pragma unroll
            for (int u = 0; u < 4; u++) yacc[u][q] += x2[u] * fw;
        }
    }

#pragma unroll
    for (int u = 0; u < 4; u++)
#pragma unroll
        for (int q = 0; q < 10; q++)
            g_y[(base + u) * 10 + q] = leaky(yacc[u][q]);
}

// ---------------- K5: fc2 split-K GEMM (256x58500)@(58500x64) ----------------
#define KSPLIT 74
#define MT 64
#define KC 16
__global__ __launch_bounds__(256)
void k_fc2(const float* __restrict__ w2) {
    __shared__ float ys[KC][68];
    __shared__ float ws[KC][68];
    int m0 = blockIdx.x * MT;                       // batch tile
    int kchunk = (K2DIM + KSPLIT - 1) / KSPLIT;     // 791
    int ks = blockIdx.y * kchunk;
    int ke = min(ks + kchunk, K2DIM);
    int tid = threadIdx.x;
    int tr = tid & 15, tc = tid >> 4;
    int lk = tid & 15, lr = tid >> 4;
    float acc[4][4];
#pragma unroll
    for (int u = 0; u < 4; u++)
#pragma unroll
        for (int w = 0; w < 4; w++) acc[u][w] = 0.f;

    for (int k0 = ks; k0 < ke; k0 += KC) {
        int k = k0 + lk;
        bool ok = (k < ke);
#pragma unroll
        for (int u = 0; u < 4; u++) {
            int r = lr + 16 * u;   // row within tile (batch for ys, output for ws)
            ys[lk][r] = ok ? g_y[(size_t)(m0 + r) * K2DIM + k] : 0.f;
            ws[lk][r] = ok ? __ldg(w2 + (size_t)r * K2DIM + k) : 0.f;
        }
        __syncthreads();
#pragma unroll
        for (int kk = 0; kk < KC; kk++) {
            float4 yv = *(const float4*)&ys[kk][tr * 4];
            float4 wv = *(const float4*)&ws[kk][tc * 4];
            acc[0][0] += yv.x * wv.x; acc[0][1] += yv.x * wv.y; acc[0][2] += yv.x * wv.z; acc[0][3] += yv.x * wv.w;
            acc[1][0] += yv.y * wv.x; acc[1][1] += yv.y * wv.y; acc[1][2] += yv.y * wv.z; acc[1][3] += yv.y * wv.w;
            acc[2][0] += yv.z * wv.x; acc[2][1] += yv.z * wv.y; acc[2][2] += yv.z * wv.z; acc[2][3] += yv.z * wv.w;
            acc[3][0] += yv.w * wv.x; acc[3][1] += yv.w * wv.y; acc[3][2] += yv.w * wv.z; acc[3][3] += yv.w * wv.w;
        }
        __syncthreads();
    }
#pragma unroll
    for (int u = 0; u < 4; u++)
#pragma unroll
        for (int w = 0; w < 4; w++)
            atomicAdd(&g_acc[(m0 + tr * 4 + u) * NOUT + tc * 4 + w], acc[u][w]);
}

// ---------------- K6: bias + softmax ----------------
__global__ void k_softmax(const float* __restrict__ fc2b, float* __restrict__ out) {
    int b = blockIdx.x * 8 + (threadIdx.x >> 5);
    int lane = threadIdx.x & 31;
    if (b >= BATCH) return;
    float v0 = g_acc[b * 64 + lane]      + __ldg(fc2b + lane);
    float v1 = g_acc[b * 64 + 32 + lane] + __ldg(fc2b + 32 + lane);
    float m = fmaxf(v0, v1);
#pragma unroll
    for (int o = 16; o; o >>= 1) m = fmaxf(m, __shfl_xor_sync(0xffffffffu, m, o));
    float e0 = expf(v0 - m), e1 = expf(v1 - m);
    float s = e0 + e1;
#pragma unroll
    for (int o = 16; o; o >>= 1) s += __shfl_xor_sync(0xffffffffu, s, o);
    float inv = 1.f / s;
    out[b * 64 + lane]      = e0 * inv;
    out[b * 64 + 32 + lane] = e1 * inv;
}

// ---------------- launch ----------------
extern "C" void kernel_launch(void* const* d_in, const int* in_sizes, int n_in,
                              void* d_out, int out_size) {
    const float* verts = (const float*)d_in[0];
    const int2*  edges = (const int2*)d_in[1];
    const float* w0a  = (const float*)d_in[2];
    const float* b0a  = (const float*)d_in[3];
    const float* w1a  = (const float*)d_in[4];
    const float* b1a  = (const float*)d_in[5];
    const float* w0b  = (const float*)d_in[6];
    const float* b0b  = (const float*)d_in[7];
    const float* w1b  = (const float*)d_in[8];
    const float* b1b  = (const float*)d_in[9];
    const float* fc1w = (const float*)d_in[10];
    const float* fc1b = (const float*)d_in[11];
    const float* fc2w = (const float*)d_in[12];
    const float* fc2b = (const float*)d_in[13];

    k_zero<<<4096, 256>>>();
    k_scatter_a<<<(E_TOTAL + 255) / 256, 256>>>(verts, edges);
    k_x1<<<(V_TOTAL + 255) / 256, 256>>>(verts, w0a, b0a, w1a, b1a);
    k_scatter_b<<<(E_TOTAL + 255) / 256, 256>>>(edges);
    k_vertex<<<(V_TOTAL / 4 + 255) / 256, 256>>>(w0b, b0b, w1b, b1b, fc1w, fc1b);
    k_fc2<<<dim3(4, KSPLIT), 256>>>(fc2w);
    k_softmax<<<32, 256>>>(fc2b, (float*)d_out);
}

// round 2
// speedup vs baseline: 1.0140x; 1.0140x over previous
#include <cuda_runtime.h>
#include <cstdint>

#define V_TOTAL 1497600
#define E_TOTAL 4492800
#define BATCH   256
#define VPM     5850
#define K2DIM   58500   /* VPM*10 */
#define NOUT    64
#define NEG     0.01f

// ---------------- scratch (static __device__, no allocations) ----------------
__device__ float4 g_vp[V_TOTAL];            // verts padded to 16B rows
__device__ float4 g_sa[V_TOTAL];            // layer-a neighbor sums (xyz) + degree (w)
__device__ float4 g_x1[V_TOTAL * 2];        // layer-a output, 32B rows: {x0..x3},{x4,0,0,0}
__device__ float4 g_sb[V_TOTAL * 2];        // layer-b neighbor sums, 32B rows: {s0..s3},{s4,_,_,_}
__device__ float  g_y[V_TOTAL * 10];        // fc1 output (post-leaky)
__device__ float  g_acc[BATCH * NOUT];      // fc2 split-K accumulator

// ---------------- vector reductions ----------------
__device__ __forceinline__ void red_add_v4(float4* addr, float a, float b, float c, float d) {
    asm volatile("red.global.add.v4.f32 [%0], {%1,%2,%3,%4};"
                 :: "l"(addr), "f"(a), "f"(b), "f"(c), "f"(d) : "memory");
}
__device__ __forceinline__ void red_add_f32(float* addr, float a) {
    asm volatile("red.global.add.f32 [%0], %1;" :: "l"(addr), "f"(a) : "memory");
}
__device__ __forceinline__ float leaky(float t) { return t >= 0.f ? t : NEG * t; }

// ---------------- K0: zero accumulators + build padded verts ----------------
__global__ void k_zero(const float* __restrict__ verts) {
    int i = blockIdx.x * blockDim.x + threadIdx.x;
    int stride = gridDim.x * blockDim.x;
    float4 z4 = make_float4(0.f, 0.f, 0.f, 0.f);
    for (int v = i; v < V_TOTAL; v += stride) {
        g_vp[v] = make_float4(verts[3 * v + 0], verts[3 * v + 1], verts[3 * v + 2], 0.f);
        g_sa[v] = z4;
        g_sb[2 * v + 0] = z4;
        g_sb[2 * v + 1] = z4;
    }
    if (i < BATCH * NOUT) g_acc[i] = 0.f;
}

// ---------------- K1: scatter raw verts + degree (1 sector per gather/scatter) ----------------
__global__ void k_scatter_a(const int2* __restrict__ edges) {
    int e = blockIdx.x * blockDim.x + threadIdx.x;
    if (e >= E_TOTAL) return;
    int2 ij = edges[e];
    float4 vi = __ldg(g_vp + ij.x);
    float4 vj = __ldg(g_vp + ij.y);
    red_add_v4(g_sa + ij.x, vj.x, vj.y, vj.z, 1.f);
    red_add_v4(g_sa + ij.y, vi.x, vi.y, vi.z, 1.f);
}

// ---------------- K2: x1 = leaky(verts@w0a^T + b0a + sa@w1a^T + deg*b1a), padded rows ----------------
__global__ void k_x1(const float* __restrict__ w0a, const float* __restrict__ b0a,
                     const float* __restrict__ w1a, const float* __restrict__ b1a) {
    int v = blockIdx.x * blockDim.x + threadIdx.x;
    if (v >= V_TOTAL) return;
    float4 p = g_vp[v];
    float4 s = g_sa[v];
    float o[5];
#pragma unroll
    for (int m = 0; m < 5; m++) {
        float t = __ldg(b0a + m) + s.w * __ldg(b1a + m);
        t += p.x * __ldg(w0a + 3 * m + 0) + p.y * __ldg(w0a + 3 * m + 1) + p.z * __ldg(w0a + 3 * m + 2);
        t += s.x * __ldg(w1a + 3 * m + 0) + s.y * __ldg(w1a + 3 * m + 1) + s.z * __ldg(w1a + 3 * m + 2);
        o[m] = leaky(t);
    }
    g_x1[2 * v + 0] = make_float4(o[0], o[1], o[2], o[3]);
    g_x1[2 * v + 1] = make_float4(o[4], 0.f, 0.f, 0.f);
}

// ---------------- K3: scatter x1 (1 sector gather, 1 sector scatter per endpoint) ----------------
__global__ void k_scatter_b(const int2* __restrict__ edges) {
    int e = blockIdx.x * blockDim.x + threadIdx.x;
    if (e >= E_TOTAL) return;
    int2 ij = edges[e];
    float4 a0 = __ldg(g_x1 + 2 * ij.x);
    float  a4 = __ldg((const float*)(g_x1 + 2 * ij.x + 1));
    float4 c0 = __ldg(g_x1 + 2 * ij.y);
    float  c4 = __ldg((const float*)(g_x1 + 2 * ij.y + 1));
    red_add_v4(g_sb + 2 * ij.x, c0.x, c0.y, c0.z, c0.w);
    red_add_f32((float*)(g_sb + 2 * ij.x + 1), c4);
    red_add_v4(g_sb + 2 * ij.y, a0.x, a0.y, a0.z, a0.w);
    red_add_f32((float*)(g_sb + 2 * ij.y + 1), a4);
}

// ---------------- K4: fused layer-b combine + fc1 (4 verts/thread) ----------------
__global__ __launch_bounds__(256)
void k_vertex(const float* __restrict__ w0b, const float* __restrict__ b0b,
              const float* __restrict__ w1b, const float* __restrict__ b1b,
              const float* __restrict__ fc1w, const float* __restrict__ fc1b) {
    __shared__ float s_w0b[100], s_w1b[100], s_b0b[20], s_b1b[20], s_f1[200], s_f1b[16];
    int tid = threadIdx.x;
    if (tid < 100) { s_w0b[tid] = w0b[tid]; s_w1b[tid] = w1b[tid]; }
    if (tid < 20)  { s_b0b[tid] = b0b[tid]; s_b1b[tid] = b1b[tid]; }
    if (tid < 200) s_f1[tid] = fc1w[tid];
    if (tid < 10)  s_f1b[tid] = fc1b[tid];
    __syncthreads();

    int base = (blockIdx.x * blockDim.x + threadIdx.x) * 4;
    if (base >= V_TOTAL) return;   // V_TOTAL % 4 == 0

    float x1[4][5], sb[4][5], deg[4], yacc[4][10];
#pragma unroll
    for (int u = 0; u < 4; u++) {
        int v = base + u;
        float4 xa = g_x1[2 * v], xb = g_x1[2 * v + 1];
        x1[u][0] = xa.x; x1[u][1] = xa.y; x1[u][2] = xa.z; x1[u][3] = xa.w; x1[u][4] = xb.x;
        float4 sa4 = g_sb[2 * v], sb4 = g_sb[2 * v + 1];
        sb[u][0] = sa4.x; sb[u][1] = sa4.y; sb[u][2] = sa4.z; sb[u][3] = sa4.w; sb[u][4] = sb4.x;
        deg[u] = g_sa[v].w;
#pragma unroll
        for (int q = 0; q < 10; q++) yacc[u][q] = s_f1b[q];
    }

#pragma unroll
    for (int n = 0; n < 20; n++) {
        float w0r[5], w1r[5];
#pragma unroll
        for (int m = 0; m < 5; m++) { w0r[m] = s_w0b[5 * n + m]; w1r[m] = s_w1b[5 * n + m]; }
        float bb0 = s_b0b[n], bb1 = s_b1b[n];
        float x2[4];
#pragma unroll
        for (int u = 0; u < 4; u++) {
            float t = bb0 + deg[u] * bb1;
#pragma unroll
            for (int m = 0; m < 5; m++) t += x1[u][m] * w0r[m] + sb[u][m] * w1r[m];
            x2[u] = leaky(t);
        }
#pragma unroll
        for (int q = 0; q < 10; q++) {
            float fw = s_f1[20 * q + n];
#pragma unroll
            for (int u = 0; u < 4; u++) yacc[u][q] += x2[u] * fw;
        }
    }

#pragma unroll
    for (int u = 0; u < 4; u++)
#pragma unroll
        for (int q = 0; q < 10; q++)
            g_y[(base + u) * 10 + q] = leaky(yacc[u][q]);
}

// ---------------- K5: fc2 split-K GEMM (256x58500)@(58500x64) ----------------
#define KSPLIT 148
#define KCHUNK 400    /* multiple of 16; 148*400 = 59200 >= 58500 */
__global__ __launch_bounds__(256)
void k_fc2(const float* __restrict__ w2) {
    __shared__ float ys[16][68];
    __shared__ float ws[16][68];
    int m0 = blockIdx.x * 64;
    int ks = blockIdx.y * KCHUNK;
    int ke = min(ks + KCHUNK, K2DIM);
    int tid = threadIdx.x;
    int row = tid >> 2, kq = tid & 3;     // loader: one float4 of k per thread per array
    int tr = tid & 15, tc = tid >> 4;     // compute: 4x4 micro-tile
    float acc[4][4];
#pragma unroll
    for (int u = 0; u < 4; u++)
#pragma unroll
        for (int w = 0; w < 4; w++) acc[u][w] = 0.f;

    for (int k0 = ks; k0 < ke; k0 += 16) {
        int k = k0 + kq * 4;
        float4 yv = make_float4(0.f, 0.f, 0.f, 0.f);
        float4 wv = yv;
        if (k < ke) {   // ke % 4 == 0, so whole float4 is in-range
            yv = *(const float4*)(g_y + (size_t)(m0 + row) * K2DIM + k);
            wv = __ldg((const float4*)(w2 + (size_t)row * K2DIM + k));
        }
        __syncthreads();
        ys[kq * 4 + 0][row] = yv.x; ys[kq * 4 + 1][row] = yv.y;
        ys[kq * 4 + 2][row] = yv.z; ys[kq * 4 + 3][row] = yv.w;
        ws[kq * 4 + 0][row] = wv.x; ws[kq * 4 + 1][row] = wv.y;
        ws[kq * 4 + 2][row] = wv.z; ws[kq * 4 + 3][row] = wv.w;
        __syncthreads();
#pragma unroll
        for (int kk = 0; kk < 16; kk++) {
            float4 y4 = *(const float4*)&ys[kk][tr * 4];
            float4 w4 = *(const float4*)&ws[kk][tc * 4];
            acc[0][0] += y4.x * w4.x; acc[0][1] += y4.x * w4.y; acc[0][2] += y4.x * w4.z; acc[0][3] += y4.x * w4.w;
            acc[1][0] += y4.y * w4.x; acc[1][1] += y4.y * w4.y; acc[1][2] += y4.y * w4.z; acc[1][3] += y4.y * w4.w;
            acc[2][0] += y4.z * w4.x; acc[2][1] += y4.z * w4.y; acc[2][2] += y4.z * w4.z; acc[2][3] += y4.z * w4.w;
            acc[3][0] += y4.w * w4.x; acc[3][1] += y4.w * w4.y; acc[3][2] += y4.w * w4.z; acc[3][3] += y4.w * w4.w;
        }
    }
#pragma unroll
    for (int u = 0; u < 4; u++)
#pragma unroll
        for (int w = 0; w < 4; w++)
            atomicAdd(&g_acc[(m0 + tr * 4 + u) * NOUT + tc * 4 + w], acc[u][w]);
}

// ---------------- K6: bias + softmax ----------------
__global__ void k_softmax(const float* __restrict__ fc2b, float* __restrict__ out) {
    int b = blockIdx.x * 8 + (threadIdx.x >> 5);
    int lane = threadIdx.x & 31;
    if (b >= BATCH) return;
    float v0 = g_acc[b * 64 + lane]      + __ldg(fc2b + lane);
    float v1 = g_acc[b * 64 + 32 + lane] + __ldg(fc2b + 32 + lane);
    float m = fmaxf(v0, v1);
#pragma unroll
    for (int o = 16; o; o >>= 1) m = fmaxf(m, __shfl_xor_sync(0xffffffffu, m, o));
    float e0 = expf(v0 - m), e1 = expf(v1 - m);
    float s = e0 + e1;
#pragma unroll
    for (int o = 16; o; o >>= 1) s += __shfl_xor_sync(0xffffffffu, s, o);
    float inv = 1.f / s;
    out[b * 64 + lane]      = e0 * inv;
    out[b * 64 + 32 + lane] = e1 * inv;
}

// ---------------- launch ----------------
extern "C" void kernel_launch(void* const* d_in, const int* in_sizes, int n_in,
                              void* d_out, int out_size) {
    const float* verts = (const float*)d_in[0];
    const int2*  edges = (const int2*)d_in[1];
    const float* w0a  = (const float*)d_in[2];
    const float* b0a  = (const float*)d_in[3];
    const float* w1a  = (const float*)d_in[4];
    const float* b1a  = (const float*)d_in[5];
    const float* w0b  = (const float*)d_in[6];
    const float* b0b  = (const float*)d_in[7];
    const float* w1b  = (const float*)d_in[8];
    const float* b1b  = (const float*)d_in[9];
    const float* fc1w = (const float*)d_in[10];
    const float* fc1b = (const float*)d_in[11];
    const float* fc2w = (const float*)d_in[12];
    const float* fc2b = (const float*)d_in[13];

    k_zero<<<4096, 256>>>(verts);
    k_scatter_a<<<(E_TOTAL + 255) / 256, 256>>>(edges);
    k_x1<<<(V_TOTAL + 255) / 256, 256>>>(w0a, b0a, w1a, b1a);
    k_scatter_b<<<(E_TOTAL + 255) / 256, 256>>>(edges);
    k_vertex<<<(V_TOTAL / 4 + 255) / 256, 256>>>(w0b, b0b, w1b, b1b, fc1w, fc1b);
    k_fc2<<<dim3(4, KSPLIT), 256>>>(fc2w);
    k_softmax<<<32, 256>>>(fc2b, (float*)d_out);
}

// round 3
// speedup vs baseline: 1.1002x; 1.0849x over previous
#include <cuda_runtime.h>
#include <cstdint>

#define V_TOTAL 1497600
#define E_TOTAL 4492800
#define BATCH   256
#define VPM     5850
#define K2DIM   58500   /* VPM*10 */
#define NOUT    64
#define NEG     0.01f

// ---------------- scratch ----------------
__device__ float4 g_vp[V_TOTAL];            // verts padded to 16B rows
__device__ float4 g_sa[V_TOTAL];            // layer-a neighbor sums (xyz) + degree (w)
__device__ float4 g_x1[V_TOTAL * 2];        // layer-a output, 32B rows: {x0..x3},{x4,0,0,0}
__device__ float4 g_sb[V_TOTAL * 2];        // layer-b sums, 32B rows: {s0..s3},{s4,deg,0,0}
__device__ float  g_y[V_TOTAL * 10];        // fc1 output (post-leaky)
__device__ float  g_acc[BATCH * NOUT];      // fc2 split-K accumulator

// ---------------- helpers ----------------
__device__ __forceinline__ void red_add_v4(float4* addr, float a, float b, float c, float d) {
    asm volatile("red.global.add.v4.f32 [%0], {%1,%2,%3,%4};"
                 :: "l"(addr), "f"(a), "f"(b), "f"(c), "f"(d) : "memory");
}
__device__ __forceinline__ void red_add_f32(float* addr, float a) {
    asm volatile("red.global.add.f32 [%0], %1;" :: "l"(addr), "f"(a) : "memory");
}
__device__ __forceinline__ float leaky(float t) { return t >= 0.f ? t : NEG * t; }

typedef unsigned long long u64t;
__device__ __forceinline__ u64t pk2(float a, float b) {
    u64t r; asm("mov.b64 %0,{%1,%2};" : "=l"(r) : "f"(a), "f"(b)); return r;
}
__device__ __forceinline__ void fma2(u64t& a, u64t x, u64t y) {
    asm("fma.rn.f32x2 %0,%1,%2,%0;" : "+l"(a) : "l"(x), "l"(y));
}
__device__ __forceinline__ void upk2(u64t d, float& a, float& b) {
    asm("mov.b64 {%0,%1},%2;" : "=f"(a), "=f"(b) : "l"(d));
}

// ---------------- K0: init g_vp, zero g_sa / g_acc ----------------
__global__ void k_prep(const float* __restrict__ verts) {
    int i = blockIdx.x * blockDim.x + threadIdx.x;
    int stride = gridDim.x * blockDim.x;
    float4 z4 = make_float4(0.f, 0.f, 0.f, 0.f);
    for (int v = i; v < V_TOTAL; v += stride) {
        g_vp[v] = make_float4(verts[3 * v + 0], verts[3 * v + 1], verts[3 * v + 2], 0.f);
        g_sa[v] = z4;
    }
    if (i < BATCH * NOUT) g_acc[i] = 0.f;
}

// ---------------- K1: scatter raw verts + degree ----------------
__global__ void k_scatter_a(const int2* __restrict__ edges) {
    int e = blockIdx.x * blockDim.x + threadIdx.x;
    if (e >= E_TOTAL) return;
    int2 ij = edges[e];
    float4 vi = __ldg(g_vp + ij.x);
    float4 vj = __ldg(g_vp + ij.y);
    red_add_v4(g_sa + ij.x, vj.x, vj.y, vj.z, 1.f);
    red_add_v4(g_sa + ij.y, vi.x, vi.y, vi.z, 1.f);
}

// ---------------- K2: x1 = leaky(...) ; also init g_sb rows {0,0,0,0},{0,deg,0,0} ----------------
__global__ void k_x1(const float* __restrict__ w0a, const float* __restrict__ b0a,
                     const float* __restrict__ w1a, const float* __restrict__ b1a) {
    int v = blockIdx.x * blockDim.x + threadIdx.x;
    if (v >= V_TOTAL) return;
    float4 p = g_vp[v];
    float4 s = g_sa[v];
    float o[5];
#pragma unroll
    for (int m = 0; m < 5; m++) {
        float t = __ldg(b0a + m) + s.w * __ldg(b1a + m);
        t += p.x * __ldg(w0a + 3 * m + 0) + p.y * __ldg(w0a + 3 * m + 1) + p.z * __ldg(w0a + 3 * m + 2);
        t += s.x * __ldg(w1a + 3 * m + 0) + s.y * __ldg(w1a + 3 * m + 1) + s.z * __ldg(w1a + 3 * m + 2);
        o[m] = leaky(t);
    }
    g_x1[2 * v + 0] = make_float4(o[0], o[1], o[2], o[3]);
    g_x1[2 * v + 1] = make_float4(o[4], 0.f, 0.f, 0.f);
    g_sb[2 * v + 0] = make_float4(0.f, 0.f, 0.f, 0.f);
    g_sb[2 * v + 1] = make_float4(0.f, s.w, 0.f, 0.f);   // pack degree for k_vertex
}

// ---------------- K3: scatter x1, destination-half partitioned (2 launches) ----------------
__global__ void k_scatter_b(const int2* __restrict__ edges, int lo, int hi) {
    int e = blockIdx.x * blockDim.x + threadIdx.x;
    if (e >= E_TOTAL) return;
    int2 ij = edges[e];
    if (ij.x >= lo && ij.x < hi) {
        float4 c0 = __ldg(g_x1 + 2 * ij.y);
        float  c4 = __ldg((const float*)(g_x1 + 2 * ij.y + 1));
        red_add_v4(g_sb + 2 * ij.x, c0.x, c0.y, c0.z, c0.w);
        red_add_f32((float*)(g_sb + 2 * ij.x + 1), c4);
    }
    if (ij.y >= lo && ij.y < hi) {
        float4 a0 = __ldg(g_x1 + 2 * ij.x);
        float  a4 = __ldg((const float*)(g_x1 + 2 * ij.x + 1));
        red_add_v4(g_sb + 2 * ij.y, a0.x, a0.y, a0.z, a0.w);
        red_add_f32((float*)(g_sb + 2 * ij.y + 1), a4);
    }
}

// ---------------- K4: fused layer-b combine + fc1 (4 verts/thread, packed f32x2 fc1 acc) ----------------
__global__ __launch_bounds__(256)
void k_vertex(const float* __restrict__ w0b, const float* __restrict__ b0b,
              const float* __restrict__ w1b, const float* __restrict__ b1b,
              const float* __restrict__ fc1w, const float* __restrict__ fc1b) {
    __shared__ float s_w0b[100], s_w1b[100], s_b0b[20], s_b1b[20], s_f1b[16];
    __shared__ u64t  s_f1d[200];   // fc1w duplicated into f32x2 pairs
    int tid = threadIdx.x;
    if (tid < 100) { s_w0b[tid] = w0b[tid]; s_w1b[tid] = w1b[tid]; }
    if (tid < 20)  { s_b0b[tid] = b0b[tid]; s_b1b[tid] = b1b[tid]; }
    if (tid < 200) { float f = fc1w[tid]; s_f1d[tid] = pk2(f, f); }
    if (tid < 10)  s_f1b[tid] = fc1b[tid];
    __syncthreads();

    int base = (blockIdx.x * blockDim.x + threadIdx.x) * 4;
    if (base >= V_TOTAL) return;   // V_TOTAL % 4 == 0

    float x1[4][5], sb[4][5], deg[4];
    u64t yac[10][2];               // [q][u-pair]
#pragma unroll
    for (int u = 0; u < 4; u++) {
        int v = base + u;
        float4 xa = g_x1[2 * v], xb = g_x1[2 * v + 1];
        x1[u][0] = xa.x; x1[u][1] = xa.y; x1[u][2] = xa.z; x1[u][3] = xa.w; x1[u][4] = xb.x;
        float4 sa4 = g_sb[2 * v], sb4 = g_sb[2 * v + 1];
        sb[u][0] = sa4.x; sb[u][1] = sa4.y; sb[u][2] = sa4.z; sb[u][3] = sa4.w; sb[u][4] = sb4.x;
        deg[u] = sb4.y;
    }
#pragma unroll
    for (int q = 0; q < 10; q++) {
        float bq = s_f1b[q];
        yac[q][0] = pk2(bq, bq);
        yac[q][1] = pk2(bq, bq);
    }

#pragma unroll
    for (int n = 0; n < 20; n++) {
        float w0r[5], w1r[5];
#pragma unroll
        for (int m = 0; m < 5; m++) { w0r[m] = s_w0b[5 * n + m]; w1r[m] = s_w1b[5 * n + m]; }
        float bb0 = s_b0b[n], bb1 = s_b1b[n];
        float x2[4];
#pragma unroll
        for (int u = 0; u < 4; u++) {
            float t = bb0 + deg[u] * bb1;
#pragma unroll
            for (int m = 0; m < 5; m++) t += x1[u][m] * w0r[m] + sb[u][m] * w1r[m];
            x2[u] = leaky(t);
        }
        u64t xp0 = pk2(x2[0], x2[1]);
        u64t xp1 = pk2(x2[2], x2[3]);
#pragma unroll
        for (int q = 0; q < 10; q++) {
            u64t fw2 = s_f1d[20 * q + n];
            fma2(yac[q][0], xp0, fw2);
            fma2(yac[q][1], xp1, fw2);
        }
    }

    float yo[4][10];
#pragma unroll
    for (int q = 0; q < 10; q++) {
        float a, b;
        upk2(yac[q][0], a, b); yo[0][q] = leaky(a); yo[1][q] = leaky(b);
        upk2(yac[q][1], a, b); yo[2][q] = leaky(a); yo[3][q] = leaky(b);
    }
    // 40 contiguous floats starting at base*10 (16B aligned since base%4==0)
    float4* dst = (float4*)(g_y + (size_t)base * 10);
#pragma unroll
    for (int i = 0; i < 10; i++) {
        int t0 = 4 * i;
        dst[i] = make_float4(yo[t0 / 10][t0 % 10], yo[(t0 + 1) / 10][(t0 + 1) % 10],
                             yo[(t0 + 2) / 10][(t0 + 2) % 10], yo[(t0 + 3) / 10][(t0 + 3) % 10]);
    }
}

// ---------------- K5: fc2 split-K GEMM with packed f32x2 FMAs ----------------
#define KSPLIT 148
#define KCHUNK 400    /* multiple of 16; 148*400 >= 58500 */
__global__ __launch_bounds__(256)
void k_fc2(const float* __restrict__ w2) {
    __shared__ float ys[16][68];     // [k][batch-row]
    __shared__ u64t  ws2[16][64];    // [k][out-col], each value duplicated (w,w)
    int m0 = blockIdx.x * 64;
    int ks = blockIdx.y * KCHUNK;
    int ke = min(ks + KCHUNK, K2DIM);
    int tid = threadIdx.x;
    int row = tid >> 2, kq = tid & 3;     // loader
    int tr = tid & 15, tc = tid >> 4;     // compute: batch-quad x out-quad
    u64t acc[4][2];                        // [o][batch-pair]
    u64t z = pk2(0.f, 0.f);
#pragma unroll
    for (int o = 0; o < 4; o++) { acc[o][0] = z; acc[o][1] = z; }

    for (int k0 = ks; k0 < ke; k0 += 16) {
        int k = k0 + kq * 4;
        float4 yv = make_float4(0.f, 0.f, 0.f, 0.f);
        float4 wv = yv;
        if (k < ke) {   // ke % 4 == 0
            yv = *(const float4*)(g_y + (size_t)(m0 + row) * K2DIM + k);
            wv = __ldg((const float4*)(w2 + (size_t)row * K2DIM + k));
        }
        __syncthreads();
        ys[kq * 4 + 0][row] = yv.x; ys[kq * 4 + 1][row] = yv.y;
        ys[kq * 4 + 2][row] = yv.z; ys[kq * 4 + 3][row] = yv.w;
        ws2[kq * 4 + 0][row] = pk2(wv.x, wv.x); ws2[kq * 4 + 1][row] = pk2(wv.y, wv.y);
        ws2[kq * 4 + 2][row] = pk2(wv.z, wv.z); ws2[kq * 4 + 3][row] = pk2(wv.w, wv.w);
        __syncthreads();
#pragma unroll
        for (int kk = 0; kk < 16; kk++) {
            ulonglong2 yp = *(const ulonglong2*)&ys[kk][tr * 4];   // (y0,y1),(y2,y3)
#pragma unroll
            for (int o = 0; o < 4; o++) {
                u64t w = ws2[kk][tc * 4 + o];                      // broadcast
                fma2(acc[o][0], yp.x, w);
                fma2(acc[o][1], yp.y, w);
            }
        }
    }
#pragma unroll
    for (int o = 0; o < 4; o++) {
        float a, b;
        upk2(acc[o][0], a, b);
        atomicAdd(&g_acc[(m0 + tr * 4 + 0) * NOUT + tc * 4 + o], a);
        atomicAdd(&g_acc[(m0 + tr * 4 + 1) * NOUT + tc * 4 + o], b);
        upk2(acc[o][1], a, b);
        atomicAdd(&g_acc[(m0 + tr * 4 + 2) * NOUT + tc * 4 + o], a);
        atomicAdd(&g_acc[(m0 + tr * 4 + 3) * NOUT + tc * 4 + o], b);
    }
}

// ---------------- K6: bias + softmax ----------------
__global__ void k_softmax(const float* __restrict__ fc2b, float* __restrict__ out) {
    int b = blockIdx.x * 8 + (threadIdx.x >> 5);
    int lane = threadIdx.x & 31;
    if (b >= BATCH) return;
    float v0 = g_acc[b * 64 + lane]      + __ldg(fc2b + lane);
    float v1 = g_acc[b * 64 + 32 + lane] + __ldg(fc2b + 32 + lane);
    float m = fmaxf(v0, v1);
#pragma unroll
    for (int o = 16; o; o >>= 1) m = fmaxf(m, __shfl_xor_sync(0xffffffffu, m, o));
    float e0 = expf(v0 - m), e1 = expf(v1 - m);
    float s = e0 + e1;
#pragma unroll
    for (int o = 16; o; o >>= 1) s += __shfl_xor_sync(0xffffffffu, s, o);
    float inv = 1.f / s;
    out[b * 64 + lane]      = e0 * inv;
    out[b * 64 + 32 + lane] = e1 * inv;
}

// ---------------- launch ----------------
extern "C" void kernel_launch(void* const* d_in, const int* in_sizes, int n_in,
                              void* d_out, int out_size) {
    const float* verts = (const float*)d_in[0];
    const int2*  edges = (const int2*)d_in[1];
    const float* w0a  = (const float*)d_in[2];
    const float* b0a  = (const float*)d_in[3];
    const float* w1a  = (const float*)d_in[4];
    const float* b1a  = (const float*)d_in[5];
    const float* w0b  = (const float*)d_in[6];
    const float* b0b  = (const float*)d_in[7];
    const float* w1b  = (const float*)d_in[8];
    const float* b1b  = (const float*)d_in[9];
    const float* fc1w = (const float*)d_in[10];
    const float* fc1b = (const float*)d_in[11];
    const float* fc2w = (const float*)d_in[12];
    const float* fc2b = (const float*)d_in[13];

    const int HALF = V_TOTAL / 2;
    k_prep<<<4096, 256>>>(verts);
    k_scatter_a<<<(E_TOTAL + 255) / 256, 256>>>(edges);
    k_x1<<<(V_TOTAL + 255) / 256, 256>>>(w0a, b0a, w1a, b1a);
    k_scatter_b<<<(E_TOTAL + 255) / 256, 256>>>(edges, 0, HALF);
    k_scatter_b<<<(E_TOTAL + 255) / 256, 256>>>(edges, HALF, V_TOTAL);
    k_vertex<<<(V_TOTAL / 4 + 255) / 256, 256>>>(w0b, b0b, w1b, b1b, fc1w, fc1b);
    k_fc2<<<dim3(4, KSPLIT), 256>>>(fc2w);
    k_softmax<<<32, 256>>>(fc2b, (float*)d_out);
}

// round 4
// speedup vs baseline: 1.3956x; 1.2686x over previous
#include <cuda_runtime.h>
#include <cuda_fp16.h>
#include <cstdint>

#define V_TOTAL 1497600
#define E_TOTAL 4492800
#define BATCH   256
#define VPM     5850
#define K2DIM   58500   /* VPM*10 */
#define NOUT    64
#define NEG     0.01f

// ---------------- scratch ----------------
__device__ float4 g_vp[V_TOTAL];            // verts padded to 16B rows
__device__ float4 g_sa[V_TOTAL];            // layer-a neighbor sums (xyz) + degree (w)
__device__ uint4  g_x1h[V_TOTAL];           // x1 as f16: {x0,x1},{x2,x3},{x4,deg},{0,0}
__device__ uint4  g_sbh[V_TOTAL];           // layer-b neighbor sums, f16, same packing
__device__ float  g_y[V_TOTAL * 10];        // fc1 output (post-leaky)
__device__ float  g_acc[BATCH * NOUT];      // fc2 split-K accumulator

// ---------------- helpers ----------------
__device__ __forceinline__ void red_add_v4(float4* addr, float a, float b, float c, float d) {
    asm volatile("red.global.add.v4.f32 [%0], {%1,%2,%3,%4};"
                 :: "l"(addr), "f"(a), "f"(b), "f"(c), "f"(d) : "memory");
}
__device__ __forceinline__ void red_add_h8(uint4* addr, uint4 v) {
    asm volatile("red.global.add.noftz.v4.f16x2 [%0], {%1,%2,%3,%4};"
                 :: "l"(addr), "r"(v.x), "r"(v.y), "r"(v.z), "r"(v.w) : "memory");
}
__device__ __forceinline__ float leaky(float t) { return t >= 0.f ? t : NEG * t; }

typedef unsigned long long u64t;
__device__ __forceinline__ u64t pk2(float a, float b) {
    u64t r; asm("mov.b64 %0,{%1,%2};" : "=l"(r) : "f"(a), "f"(b)); return r;
}
__device__ __forceinline__ void fma2(u64t& a, u64t x, u64t y) {
    asm("fma.rn.f32x2 %0,%1,%2,%0;" : "+l"(a) : "l"(x), "l"(y));
}
__device__ __forceinline__ void upk2(u64t d, float& a, float& b) {
    asm("mov.b64 {%0,%1},%2;" : "=f"(a), "=f"(b) : "l"(d));
}
__device__ __forceinline__ uint32_t h2u(__half2 h) { return *reinterpret_cast<uint32_t*>(&h); }
__device__ __forceinline__ float2 u2f2(uint32_t u) {
    __half2 h = *reinterpret_cast<__half2*>(&u);
    return __half22float2(h);
}

// ---------------- K0: init g_vp, zero g_sa / g_acc ----------------
__global__ void k_prep(const float* __restrict__ verts) {
    int i = blockIdx.x * blockDim.x + threadIdx.x;
    int stride = gridDim.x * blockDim.x;
    float4 z4 = make_float4(0.f, 0.f, 0.f, 0.f);
    for (int v = i; v < V_TOTAL; v += stride) {
        g_vp[v] = make_float4(verts[3 * v + 0], verts[3 * v + 1], verts[3 * v + 2], 0.f);
        g_sa[v] = z4;
    }
    if (i < BATCH * NOUT) g_acc[i] = 0.f;
}

// ---------------- K1: scatter raw verts + degree (f32, exact) ----------------
__global__ void k_scatter_a(const int2* __restrict__ edges) {
    int e = blockIdx.x * blockDim.x + threadIdx.x;
    if (e >= E_TOTAL) return;
    int2 ij = __ldcs(edges + e);           // streaming: don't pollute L2
    float4 vi = __ldg(g_vp + ij.x);
    float4 vj = __ldg(g_vp + ij.y);
    red_add_v4(g_sa + ij.x, vj.x, vj.y, vj.z, 1.f);
    red_add_v4(g_sa + ij.y, vi.x, vi.y, vi.z, 1.f);
}

// ---------------- K2: x1 = leaky(...) -> f16 packed rows; zero g_sbh ----------------
__global__ void k_x1(const float* __restrict__ w0a, const float* __restrict__ b0a,
                     const float* __restrict__ w1a, const float* __restrict__ b1a) {
    int v = blockIdx.x * blockDim.x + threadIdx.x;
    if (v >= V_TOTAL) return;
    float4 p = g_vp[v];
    float4 s = g_sa[v];
    float o[5];
#pragma unroll
    for (int m = 0; m < 5; m++) {
        float t = __ldg(b0a + m) + s.w * __ldg(b1a + m);
        t += p.x * __ldg(w0a + 3 * m + 0) + p.y * __ldg(w0a + 3 * m + 1) + p.z * __ldg(w0a + 3 * m + 2);
        t += s.x * __ldg(w1a + 3 * m + 0) + s.y * __ldg(w1a + 3 * m + 1) + s.z * __ldg(w1a + 3 * m + 2);
        o[m] = leaky(t);
    }
    uint4 row;
    row.x = h2u(__floats2half2_rn(o[0], o[1]));
    row.y = h2u(__floats2half2_rn(o[2], o[3]));
    row.z = h2u(__floats2half2_rn(o[4], s.w));   // degree exact (small int) in f16
    row.w = 0u;
    g_x1h[v] = row;
    g_sbh[v] = make_uint4(0u, 0u, 0u, 0u);
}

// ---------------- K3: scatter x1 (f16) — single pass, 1 gather + 1 red per endpoint ----------------
__global__ void k_scatter_b(const int2* __restrict__ edges) {
    int e = blockIdx.x * blockDim.x + threadIdx.x;
    if (e >= E_TOTAL) return;
    int2 ij = __ldcs(edges + e);
    uint4 xi = __ldg(g_x1h + ij.x);
    uint4 xj = __ldg(g_x1h + ij.y);
    red_add_h8(g_sbh + ij.x, xj);   // also sums neighbor degrees into pad slot (unused)
    red_add_h8(g_sbh + ij.y, xi);
}

// ---------------- K4: fused layer-b combine + fc1 (4 verts/thread, packed f32x2 fc1 acc) ----------------
__global__ __launch_bounds__(256)
void k_vertex(const float* __restrict__ w0b, const float* __restrict__ b0b,
              const float* __restrict__ w1b, const float* __restrict__ b1b,
              const float* __restrict__ fc1w, const float* __restrict__ fc1b) {
    __shared__ float s_w0b[100], s_w1b[100], s_b0b[20], s_b1b[20], s_f1b[16];
    __shared__ u64t  s_f1d[200];   // fc1w duplicated into f32x2 pairs
    int tid = threadIdx.x;
    if (tid < 100) { s_w0b[tid] = w0b[tid]; s_w1b[tid] = w1b[tid]; }
    if (tid < 20)  { s_b0b[tid] = b0b[tid]; s_b1b[tid] = b1b[tid]; }
    if (tid < 200) { float f = fc1w[tid]; s_f1d[tid] = pk2(f, f); }
    if (tid < 10)  s_f1b[tid] = fc1b[tid];
    __syncthreads();

    int base = (blockIdx.x * blockDim.x + threadIdx.x) * 4;
    if (base >= V_TOTAL) return;   // V_TOTAL % 4 == 0

    float x1[4][5], sb[4][5], deg[4];
    u64t yac[10][2];
#pragma unroll
    for (int u = 0; u < 4; u++) {
        int v = base + u;
        uint4 xr = g_x1h[v];
        float2 f;
        f = u2f2(xr.x); x1[u][0] = f.x; x1[u][1] = f.y;
        f = u2f2(xr.y); x1[u][2] = f.x; x1[u][3] = f.y;
        f = u2f2(xr.z); x1[u][4] = f.x; deg[u] = f.y;
        uint4 sr = g_sbh[v];
        f = u2f2(sr.x); sb[u][0] = f.x; sb[u][1] = f.y;
        f = u2f2(sr.y); sb[u][2] = f.x; sb[u][3] = f.y;
        f = u2f2(sr.z); sb[u][4] = f.x;
    }
#pragma unroll
    for (int q = 0; q < 10; q++) {
        float bq = s_f1b[q];
        yac[q][0] = pk2(bq, bq);
        yac[q][1] = pk2(bq, bq);
    }

#pragma unroll
    for (int n = 0; n < 20; n++) {
        float w0r[5], w1r[5];
#pragma unroll
        for (int m = 0; m < 5; m++) { w0r[m] = s_w0b[5 * n + m]; w1r[m] = s_w1b[5 * n + m]; }
        float bb0 = s_b0b[n], bb1 = s_b1b[n];
        float x2[4];
#pragma unroll
        for (int u = 0; u < 4; u++) {
            float t = bb0 + deg[u] * bb1;
#pragma unroll
            for (int m = 0; m < 5; m++) t += x1[u][m] * w0r[m] + sb[u][m] * w1r[m];
            x2[u] = leaky(t);
        }
        u64t xp0 = pk2(x2[0], x2[1]);
        u64t xp1 = pk2(x2[2], x2[3]);
#pragma unroll
        for (int q = 0; q < 10; q++) {
            u64t fw2 = s_f1d[20 * q + n];
            fma2(yac[q][0], xp0, fw2);
            fma2(yac[q][1], xp1, fw2);
        }
    }

    float yo[4][10];
#pragma unroll
    for (int q = 0; q < 10; q++) {
        float a, b;
        upk2(yac[q][0], a, b); yo[0][q] = leaky(a); yo[1][q] = leaky(b);
        upk2(yac[q][1], a, b); yo[2][q] = leaky(a); yo[3][q] = leaky(b);
    }
    float4* dst = (float4*)(g_y + (size_t)base * 10);
#pragma unroll
    for (int i = 0; i < 10; i++) {
        int t0 = 4 * i;
        dst[i] = make_float4(yo[t0 / 10][t0 % 10], yo[(t0 + 1) / 10][(t0 + 1) % 10],
                             yo[(t0 + 2) / 10][(t0 + 2) % 10], yo[(t0 + 3) / 10][(t0 + 3) % 10]);
    }
}

// ---------------- K5: fc2 split-K GEMM with packed f32x2 FMAs ----------------
#define KSPLIT 148
#define KCHUNK 400    /* multiple of 16; 148*400 >= 58500 */
__global__ __launch_bounds__(256)
void k_fc2(const float* __restrict__ w2) {
    __shared__ float ys[16][68];     // [k][batch-row]
    __shared__ u64t  ws2[16][64];    // [k][out-col], duplicated (w,w)
    int m0 = blockIdx.x * 64;
    int ks = blockIdx.y * KCHUNK;
    int ke = min(ks + KCHUNK, K2DIM);
    int tid = threadIdx.x;
    int row = tid >> 2, kq = tid & 3;
    int tr = tid & 15, tc = tid >> 4;
    u64t acc[4][2];
    u64t z = pk2(0.f, 0.f);
#pragma unroll
    for (int o = 0; o < 4; o++) { acc[o][0] = z; acc[o][1] = z; }

    for (int k0 = ks; k0 < ke; k0 += 16) {
        int k = k0 + kq * 4;
        float4 yv = make_float4(0.f, 0.f, 0.f, 0.f);
        float4 wv = yv;
        if (k < ke) {   // ke % 4 == 0
            yv = *(const float4*)(g_y + (size_t)(m0 + row) * K2DIM + k);
            wv = __ldg((const float4*)(w2 + (size_t)row * K2DIM + k));
        }
        __syncthreads();
        ys[kq * 4 + 0][row] = yv.x; ys[kq * 4 + 1][row] = yv.y;
        ys[kq * 4 + 2][row] = yv.z; ys[kq * 4 + 3][row] = yv.w;
        ws2[kq * 4 + 0][row] = pk2(wv.x, wv.x); ws2[kq * 4 + 1][row] = pk2(wv.y, wv.y);
        ws2[kq * 4 + 2][row] = pk2(wv.z, wv.z); ws2[kq * 4 + 3][row] = pk2(wv.w, wv.w);
        __syncthreads();
#pragma unroll
        for (int kk = 0; kk < 16; kk++) {
            ulonglong2 yp = *(const ulonglong2*)&ys[kk][tr * 4];
#pragma unroll
            for (int o = 0; o < 4; o++) {
                u64t w = ws2[kk][tc * 4 + o];
                fma2(acc[o][0], yp.x, w);
                fma2(acc[o][1], yp.y, w);
            }
        }
    }
#pragma unroll
    for (int o = 0; o < 4; o++) {
        float a, b;
        upk2(acc[o][0], a, b);
        atomicAdd(&g_acc[(m0 + tr * 4 + 0) * NOUT + tc * 4 + o], a);
        atomicAdd(&g_acc[(m0 + tr * 4 + 1) * NOUT + tc * 4 + o], b);
        upk2(acc[o][1], a, b);
        atomicAdd(&g_acc[(m0 + tr * 4 + 2) * NOUT + tc * 4 + o], a);
        atomicAdd(&g_acc[(m0 + tr * 4 + 3) * NOUT + tc * 4 + o], b);
    }
}

// ---------------- K6: bias + softmax ----------------
__global__ void k_softmax(const float* __restrict__ fc2b, float* __restrict__ out) {
    int b = blockIdx.x * 8 + (threadIdx.x >> 5);
    int lane = threadIdx.x & 31;
    if (b >= BATCH) return;
    float v0 = g_acc[b * 64 + lane]      + __ldg(fc2b + lane);
    float v1 = g_acc[b * 64 + 32 + lane] + __ldg(fc2b + 32 + lane);
    float m = fmaxf(v0, v1);
#pragma unroll
    for (int o = 16; o; o >>= 1) m = fmaxf(m, __shfl_xor_sync(0xffffffffu, m, o));
    float e0 = expf(v0 - m), e1 = expf(v1 - m);
    float s = e0 + e1;
#pragma unroll
    for (int o = 16; o; o >>= 1) s += __shfl_xor_sync(0xffffffffu, s, o);
    float inv = 1.f / s;
    out[b * 64 + lane]      = e0 * inv;
    out[b * 64 + 32 + lane] = e1 * inv;
}

// ---------------- launch ----------------
extern "C" void kernel_launch(void* const* d_in, const int* in_sizes, int n_in,
                              void* d_out, int out_size) {
    const float* verts = (const float*)d_in[0];
    const int2*  edges = (const int2*)d_in[1];
    const float* w0a  = (const float*)d_in[2];
    const float* b0a  = (const float*)d_in[3];
    const float* w1a  = (const float*)d_in[4];
    const float* b1a  = (const float*)d_in[5];
    const float* w0b  = (const float*)d_in[6];
    const float* b0b  = (const float*)d_in[7];
    const float* w1b  = (const float*)d_in[8];
    const float* b1b  = (const float*)d_in[9];
    const float* fc1w = (const float*)d_in[10];
    const float* fc1b = (const float*)d_in[11];
    const float* fc2w = (const float*)d_in[12];
    const float* fc2b = (const float*)d_in[13];

    k_prep<<<4096, 256>>>(verts);
    k_scatter_a<<<(E_TOTAL + 255) / 256, 256>>>(edges);
    k_x1<<<(V_TOTAL + 255) / 256, 256>>>(w0a, b0a, w1a, b1a);
    k_scatter_b<<<(E_TOTAL + 255) / 256, 256>>>(edges);
    k_vertex<<<(V_TOTAL / 4 + 255) / 256, 256>>>(w0b, b0b, w1b, b1b, fc1w, fc1b);
    k_fc2<<<dim3(4, KSPLIT), 256>>>(fc2w);
    k_softmax<<<32, 256>>>(fc2b, (float*)d_out);
}

// round 5
// speedup vs baseline: 1.3984x; 1.0020x over previous
#include <cuda_runtime.h>
#include <cuda_fp16.h>
#include <cstdint>

#define V_TOTAL 1497600
#define E_TOTAL 4492800
#define BATCH   256
#define VPM     5850
#define K2DIM   58500   /* VPM*10 */
#define NOUT    64
#define NEG     0.01f

// ---------------- scratch ----------------
__device__ float4 g_vp[V_TOTAL];            // verts padded to 16B rows
__device__ float4 g_sa[V_TOTAL];            // layer-a neighbor sums (xyz) + degree (w)
__device__ uint4  g_x1h[V_TOTAL];           // x1 as f16: {x0,x1},{x2,x3},{x4,deg},{0,0}
__device__ uint4  g_sbh[V_TOTAL];           // layer-b neighbor sums, f16, same packing
__device__ float  g_y[V_TOTAL * 10];        // fc1 output (post-leaky)
__device__ float  g_acc[BATCH * NOUT];      // fc2 split-K accumulator

// ---------------- helpers ----------------
__device__ __forceinline__ void red_add_v4(float4* addr, float a, float b, float c, float d) {
    asm volatile("red.global.add.v4.f32 [%0], {%1,%2,%3,%4};"
                 :: "l"(addr), "f"(a), "f"(b), "f"(c), "f"(d) : "memory");
}
__device__ __forceinline__ void red_add_h8(uint4* addr, uint4 v) {
    asm volatile("red.global.add.noftz.v4.f16x2 [%0], {%1,%2,%3,%4};"
                 :: "l"(addr), "r"(v.x), "r"(v.y), "r"(v.z), "r"(v.w) : "memory");
}
__device__ __forceinline__ float leaky(float t) { return t >= 0.f ? t : NEG * t; }

typedef unsigned long long u64t;
__device__ __forceinline__ u64t pk2(float a, float b) {
    u64t r; asm("mov.b64 %0,{%1,%2};" : "=l"(r) : "f"(a), "f"(b)); return r;
}
__device__ __forceinline__ void fma2(u64t& a, u64t x, u64t y) {
    asm("fma.rn.f32x2 %0,%1,%2,%0;" : "+l"(a) : "l"(x), "l"(y));
}
__device__ __forceinline__ void upk2(u64t d, float& a, float& b) {
    asm("mov.b64 {%0,%1},%2;" : "=f"(a), "=f"(b) : "l"(d));
}
__device__ __forceinline__ uint32_t h2u(__half2 h) { return *reinterpret_cast<uint32_t*>(&h); }
__device__ __forceinline__ float2 u2f2(uint32_t u) {
    __half2 h = *reinterpret_cast<__half2*>(&u);
    return __half22float2(h);
}

// ---------------- K0: init g_vp, zero g_sa / g_acc ----------------
__global__ void k_prep(const float* __restrict__ verts) {
    int i = blockIdx.x * blockDim.x + threadIdx.x;
    int stride = gridDim.x * blockDim.x;
    float4 z4 = make_float4(0.f, 0.f, 0.f, 0.f);
    for (int v = i; v < V_TOTAL; v += stride) {
        g_vp[v] = make_float4(verts[3 * v + 0], verts[3 * v + 1], verts[3 * v + 2], 0.f);
        g_sa[v] = z4;
    }
    if (i < BATCH * NOUT) g_acc[i] = 0.f;
}

// ---------------- K1: scatter raw verts + degree (f32, exact) ----------------
__global__ void k_scatter_a(const int2* __restrict__ edges) {
    int e = blockIdx.x * blockDim.x + threadIdx.x;
    if (e >= E_TOTAL) return;
    int2 ij = __ldcs(edges + e);           // streaming: don't pollute L2
    float4 vi = __ldg(g_vp + ij.x);
    float4 vj = __ldg(g_vp + ij.y);
    red_add_v4(g_sa + ij.x, vj.x, vj.y, vj.z, 1.f);
    red_add_v4(g_sa + ij.y, vi.x, vi.y, vi.z, 1.f);
}

// ---------------- K2: x1 = leaky(...) -> f16 packed rows; zero g_sbh ----------------
__global__ void k_x1(const float* __restrict__ w0a, const float* __restrict__ b0a,
                     const float* __restrict__ w1a, const float* __restrict__ b1a) {
    int v = blockIdx.x * blockDim.x + threadIdx.x;
    if (v >= V_TOTAL) return;
    float4 p = g_vp[v];
    float4 s = g_sa[v];
    float o[5];
#pragma unroll
    for (int m = 0; m < 5; m++) {
        float t = __ldg(b0a + m) + s.w * __ldg(b1a + m);
        t += p.x * __ldg(w0a + 3 * m + 0) + p.y * __ldg(w0a + 3 * m + 1) + p.z * __ldg(w0a + 3 * m + 2);
        t += s.x * __ldg(w1a + 3 * m + 0) + s.y * __ldg(w1a + 3 * m + 1) + s.z * __ldg(w1a + 3 * m + 2);
        o[m] = leaky(t);
    }
    uint4 row;
    row.x = h2u(__floats2half2_rn(o[0], o[1]));
    row.y = h2u(__floats2half2_rn(o[2], o[3]));
    row.z = h2u(__floats2half2_rn(o[4], s.w));   // degree exact (small int) in f16
    row.w = 0u;
    g_x1h[v] = row;
    g_sbh[v] = make_uint4(0u, 0u, 0u, 0u);
}

// ---------------- K3: scatter x1 (f16) — single pass, 1 gather + 1 red per endpoint ----------------
__global__ void k_scatter_b(const int2* __restrict__ edges) {
    int e = blockIdx.x * blockDim.x + threadIdx.x;
    if (e >= E_TOTAL) return;
    int2 ij = __ldcs(edges + e);
    uint4 xi = __ldg(g_x1h + ij.x);
    uint4 xj = __ldg(g_x1h + ij.y);
    red_add_h8(g_sbh + ij.x, xj);   // also sums neighbor degrees into pad slot (unused)
    red_add_h8(g_sbh + ij.y, xi);
}

// ---------------- K4: fused layer-b combine + fc1 (4 verts/thread, packed f32x2 fc1 acc) ----------------
__global__ __launch_bounds__(256)
void k_vertex(const float* __restrict__ w0b, const float* __restrict__ b0b,
              const float* __restrict__ w1b, const float* __restrict__ b1b,
              const float* __restrict__ fc1w, const float* __restrict__ fc1b) {
    __shared__ float s_w0b[100], s_w1b[100], s_b0b[20], s_b1b[20], s_f1b[16];
    __shared__ u64t  s_f1d[200];   // fc1w duplicated into f32x2 pairs
    int tid = threadIdx.x;
    if (tid < 100) { s_w0b[tid] = w0b[tid]; s_w1b[tid] = w1b[tid]; }
    if (tid < 20)  { s_b0b[tid] = b0b[tid]; s_b1b[tid] = b1b[tid]; }
    if (tid < 200) { float f = fc1w[tid]; s_f1d[tid] = pk2(f, f); }
    if (tid < 10)  s_f1b[tid] = fc1b[tid];
    __syncthreads();

    int base = (blockIdx.x * blockDim.x + threadIdx.x) * 4;
    if (base >= V_TOTAL) return;   // V_TOTAL % 4 == 0

    float x1[4][5], sb[4][5], deg[4];
    u64t yac[10][2];
#pragma unroll
    for (int u = 0; u < 4; u++) {
        int v = base + u;
        uint4 xr = g_x1h[v];
        float2 f;
        f = u2f2(xr.x); x1[u][0] = f.x; x1[u][1] = f.y;
        f = u2f2(xr.y); x1[u][2] = f.x; x1[u][3] = f.y;
        f = u2f2(xr.z); x1[u][4] = f.x; deg[u] = f.y;
        uint4 sr = g_sbh[v];
        f = u2f2(sr.x); sb[u][0] = f.x; sb[u][1] = f.y;
        f = u2f2(sr.y); sb[u][2] = f.x; sb[u][3] = f.y;
        f = u2f2(sr.z); sb[u][4] = f.x;
    }
#pragma unroll
    for (int q = 0; q < 10; q++) {
        float bq = s_f1b[q];
        yac[q][0] = pk2(bq, bq);
        yac[q][1] = pk2(bq, bq);
    }

#pragma unroll
    for (int n = 0; n < 20; n++) {
        float w0r[5], w1r[5];
#pragma unroll
        for (int m = 0; m < 5; m++) { w0r[m] = s_w0b[5 * n + m]; w1r[m] = s_w1b[5 * n + m]; }
        float bb0 = s_b0b[n], bb1 = s_b1b[n];
        float x2[4];
#pragma unroll
        for (int u = 0; u < 4; u++) {
            float t = bb0 + deg[u] * bb1;
#pragma unroll
            for (int m = 0; m < 5; m++) t += x1[u][m] * w0r[m] + sb[u][m] * w1r[m];
            x2[u] = leaky(t);
        }
        u64t xp0 = pk2(x2[0], x2[1]);
        u64t xp1 = pk2(x2[2], x2[3]);
#pragma unroll
        for (int q = 0; q < 10; q++) {
            u64t fw2 = s_f1d[20 * q + n];
            fma2(yac[q][0], xp0, fw2);
            fma2(yac[q][1], xp1, fw2);
        }
    }

    float yo[4][10];
#pragma unroll
    for (int q = 0; q < 10; q++) {
        float a, b;
        upk2(yac[q][0], a, b); yo[0][q] = leaky(a); yo[1][q] = leaky(b);
        upk2(yac[q][1], a, b); yo[2][q] = leaky(a); yo[3][q] = leaky(b);
    }
    float4* dst = (float4*)(g_y + (size_t)base * 10);
#pragma unroll
    for (int i = 0; i < 10; i++) {
        int t0 = 4 * i;
        dst[i] = make_float4(yo[t0 / 10][t0 % 10], yo[(t0 + 1) / 10][(t0 + 1) % 10],
                             yo[(t0 + 2) / 10][(t0 + 2) % 10], yo[(t0 + 3) / 10][(t0 + 3) % 10]);
    }
}

// ---------------- K5: fc2 split-K GEMM with packed f32x2 FMAs ----------------
#define KSPLIT 148
#define KCHUNK 400    /* multiple of 16; 148*400 >= 58500 */
__global__ __launch_bounds__(256)
void k_fc2(const float* __restrict__ w2) {
    __shared__ float ys[16][68];     // [k][batch-row]
    __shared__ u64t  ws2[16][64];    // [k][out-col], duplicated (w,w)
    int m0 = blockIdx.x * 64;
    int ks = blockIdx.y * KCHUNK;
    int ke = min(ks + KCHUNK, K2DIM);
    int tid = threadIdx.x;
    int row = tid >> 2, kq = tid & 3;
    int tr = tid & 15, tc = tid >> 4;
    u64t acc[4][2];
    u64t z = pk2(0.f, 0.f);
#pragma unroll
    for (int o = 0; o < 4; o++) { acc[o][0] = z; acc[o][1] = z; }

    for (int k0 = ks; k0 < ke; k0 += 16) {
        int k = k0 + kq * 4;
        float4 yv = make_float4(0.f, 0.f, 0.f, 0.f);
        float4 wv = yv;
        if (k < ke) {   // ke % 4 == 0
            yv = *(const float4*)(g_y + (size_t)(m0 + row) * K2DIM + k);
            wv = __ldg((const float4*)(w2 + (size_t)row * K2DIM + k));
        }
        __syncthreads();
        ys[kq * 4 + 0][row] = yv.x; ys[kq * 4 + 1][row] = yv.y;
        ys[kq * 4 + 2][row] = yv.z; ys[kq * 4 + 3][row] = yv.w;
        ws2[kq * 4 + 0][row] = pk2(wv.x, wv.x); ws2[kq * 4 + 1][row] = pk2(wv.y, wv.y);
        ws2[kq * 4 + 2][row] = pk2(wv.z, wv.z); ws2[kq * 4 + 3][row] = pk2(wv.w, wv.w);
        __syncthreads();
#pragma unroll
        for (int kk = 0; kk < 16; kk++) {
            ulonglong2 yp = *(const ulonglong2*)&ys[kk][tr * 4];
#pragma unroll
            for (int o = 0; o < 4; o++) {
                u64t w = ws2[kk][tc * 4 + o];
                fma2(acc[o][0], yp.x, w);
                fma2(acc[o][1], yp.y, w);
            }
        }
    }
#pragma unroll
    for (int o = 0; o < 4; o++) {
        float a, b;
        upk2(acc[o][0], a, b);
        atomicAdd(&g_acc[(m0 + tr * 4 + 0) * NOUT + tc * 4 + o], a);
        atomicAdd(&g_acc[(m0 + tr * 4 + 1) * NOUT + tc * 4 + o], b);
        upk2(acc[o][1], a, b);
        atomicAdd(&g_acc[(m0 + tr * 4 + 2) * NOUT + tc * 4 + o], a);
        atomicAdd(&g_acc[(m0 + tr * 4 + 3) * NOUT + tc * 4 + o], b);
    }
}

// ---------------- K6: bias + softmax ----------------
__global__ void k_softmax(const float* __restrict__ fc2b, float* __restrict__ out) {
    int b = blockIdx.x * 8 + (threadIdx.x >> 5);
    int lane = threadIdx.x & 31;
    if (b >= BATCH) return;
    float v0 = g_acc[b * 64 + lane]      + __ldg(fc2b + lane);
    float v1 = g_acc[b * 64 + 32 + lane] + __ldg(fc2b + 32 + lane);
    float m = fmaxf(v0, v1);
#pragma unroll
    for (int o = 16; o; o >>= 1) m = fmaxf(m, __shfl_xor_sync(0xffffffffu, m, o));
    float e0 = expf(v0 - m), e1 = expf(v1 - m);
    float s = e0 + e1;
#pragma unroll
    for (int o = 16; o; o >>= 1) s += __shfl_xor_sync(0xffffffffu, s, o);
    float inv = 1.f / s;
    out[b * 64 + lane]      = e0 * inv;
    out[b * 64 + 32 + lane] = e1 * inv;
}

// ---------------- launch ----------------
extern "C" void kernel_launch(void* const* d_in, const int* in_sizes, int n_in,
                              void* d_out, int out_size) {
    const float* verts = (const float*)d_in[0];
    const int2*  edges = (const int2*)d_in[1];
    const float* w0a  = (const float*)d_in[2];
    const float* b0a  = (const float*)d_in[3];
    const float* w1a  = (const float*)d_in[4];
    const float* b1a  = (const float*)d_in[5];
    const float* w0b  = (const float*)d_in[6];
    const float* b0b  = (const float*)d_in[7];
    const float* w1b  = (const float*)d_in[8];
    const float* b1b  = (const float*)d_in[9];
    const float* fc1w = (const float*)d_in[10];
    const float* fc1b = (const float*)d_in[11];
    const float* fc2w = (const float*)d_in[12];
    const float* fc2b = (const float*)d_in[13];

    k_prep<<<4096, 256>>>(verts);
    k_scatter_a<<<(E_TOTAL + 255) / 256, 256>>>(edges);
    k_x1<<<(V_TOTAL + 255) / 256, 256>>>(w0a, b0a, w1a, b1a);
    k_scatter_b<<<(E_TOTAL + 255) / 256, 256>>>(edges);
    k_vertex<<<(V_TOTAL / 4 + 255) / 256, 256>>>(w0b, b0b, w1b, b1b, fc1w, fc1b);
    k_fc2<<<dim3(4, KSPLIT), 256>>>(fc2w);
    k_softmax<<<32, 256>>>(fc2b, (float*)d_out);
}

// round 6
// speedup vs baseline: 1.4080x; 1.0069x over previous
#include <cuda_runtime.h>
#include <cuda_fp16.h>
#include <cstdint>

#define V_TOTAL 1497600
#define E_TOTAL 4492800
#define BATCH   256
#define VPM     5850
#define K2DIM   58500   /* VPM*10 */
#define NOUT    64
#define NEG     0.01f

// ---------------- scratch ----------------
__device__ uint2  g_vph[V_TOTAL];           // verts f16: {h2(x,y), h2(z,1)}
__device__ uint2  g_sah[V_TOTAL];           // layer-a sums f16: {h2(sx,sy), h2(sz,deg)}
__device__ uint4  g_x1h[V_TOTAL];           // x1 f16: {x0,x1},{x2,x3},{x4,deg},{0,0}
__device__ uint4  g_sbh[V_TOTAL];           // layer-b sums f16, same packing
__device__ unsigned g_yh2[V_TOTAL * 5];     // fc1 output f16, h2 pairs along k
__device__ float  g_acc[BATCH * NOUT];      // fc2 split-K accumulator

// ---------------- helpers ----------------
__device__ __forceinline__ void red_add_h8(uint4* addr, uint4 v) {
    asm volatile("red.global.add.noftz.v4.f16x2 [%0], {%1,%2,%3,%4};"
                 :: "l"(addr), "r"(v.x), "r"(v.y), "r"(v.z), "r"(v.w) : "memory");
}
__device__ __forceinline__ void red_add_h4(uint2* addr, uint2 v) {
    asm volatile("red.global.add.noftz.v2.f16x2 [%0], {%1,%2};"
                 :: "l"(addr), "r"(v.x), "r"(v.y) : "memory");
}
__device__ __forceinline__ float leaky(float t) { return t >= 0.f ? t : NEG * t; }

typedef unsigned long long u64t;
__device__ __forceinline__ u64t pk2(float a, float b) {
    u64t r; asm("mov.b64 %0,{%1,%2};" : "=l"(r) : "f"(a), "f"(b)); return r;
}
__device__ __forceinline__ void fma2(u64t& a, u64t x, u64t y) {
    asm("fma.rn.f32x2 %0,%1,%2,%0;" : "+l"(a) : "l"(x), "l"(y));
}
__device__ __forceinline__ void upk2(u64t d, float& a, float& b) {
    asm("mov.b64 {%0,%1},%2;" : "=f"(a), "=f"(b) : "l"(d));
}
__device__ __forceinline__ unsigned h2u(__half2 h) { return *reinterpret_cast<unsigned*>(&h); }
__device__ __forceinline__ float2 u2f2(unsigned u) {
    __half2 h = *reinterpret_cast<__half2*>(&u);
    return __half22float2(h);
}

// ---------------- K0: build f16 verts, zero g_sah / g_acc ----------------
__global__ void k_prep(const float* __restrict__ verts) {
    int i = blockIdx.x * blockDim.x + threadIdx.x;
    int stride = gridDim.x * blockDim.x;
    for (int v = i; v < V_TOTAL; v += stride) {
        float x = verts[3 * v + 0], y = verts[3 * v + 1], z = verts[3 * v + 2];
        g_vph[v] = make_uint2(h2u(__floats2half2_rn(x, y)), h2u(__floats2half2_rn(z, 1.f)));
        g_sah[v] = make_uint2(0u, 0u);
    }
    if (i < BATCH * NOUT) g_acc[i] = 0.f;
}

// ---------------- K1: scatter verts+degree (f16, 8B rows) ----------------
__global__ void k_scatter_a(const int2* __restrict__ edges) {
    int e = blockIdx.x * blockDim.x + threadIdx.x;
    if (e >= E_TOTAL) return;
    int2 ij = __ldcs(edges + e);
    uint2 vi = __ldg(g_vph + ij.x);
    uint2 vj = __ldg(g_vph + ij.y);
    red_add_h4(g_sah + ij.x, vj);
    red_add_h4(g_sah + ij.y, vi);
}

// ---------------- K2: x1 = leaky(...) -> f16 rows; zero g_sbh ----------------
__global__ void k_x1(const float* __restrict__ verts,
                     const float* __restrict__ w0a, const float* __restrict__ b0a,
                     const float* __restrict__ w1a, const float* __restrict__ b1a) {
    int v = blockIdx.x * blockDim.x + threadIdx.x;
    if (v >= V_TOTAL) return;
    float p0 = verts[3 * v + 0], p1 = verts[3 * v + 1], p2 = verts[3 * v + 2];
    uint2 sr = g_sah[v];
    float2 sxy = u2f2(sr.x), szd = u2f2(sr.y);   // {sum_x,sum_y},{sum_z,degree}
    float o[5];
#pragma unroll
    for (int m = 0; m < 5; m++) {
        float t = __ldg(b0a + m) + szd.y * __ldg(b1a + m);
        t += p0 * __ldg(w0a + 3 * m + 0) + p1 * __ldg(w0a + 3 * m + 1) + p2 * __ldg(w0a + 3 * m + 2);
        t += sxy.x * __ldg(w1a + 3 * m + 0) + sxy.y * __ldg(w1a + 3 * m + 1) + szd.x * __ldg(w1a + 3 * m + 2);
        o[m] = leaky(t);
    }
    uint4 row;
    row.x = h2u(__floats2half2_rn(o[0], o[1]));
    row.y = h2u(__floats2half2_rn(o[2], o[3]));
    row.z = h2u(__floats2half2_rn(o[4], szd.y));   // degree rides along (exact in f16)
    row.w = 0u;
    g_x1h[v] = row;
    g_sbh[v] = make_uint4(0u, 0u, 0u, 0u);
}

// ---------------- K3: scatter x1 (f16, 16B rows) ----------------
__global__ void k_scatter_b(const int2* __restrict__ edges) {
    int e = blockIdx.x * blockDim.x + threadIdx.x;
    if (e >= E_TOTAL) return;
    int2 ij = __ldcs(edges + e);
    uint4 xi = __ldg(g_x1h + ij.x);
    uint4 xj = __ldg(g_x1h + ij.y);
    red_add_h8(g_sbh + ij.x, xj);
    red_add_h8(g_sbh + ij.y, xi);
}

// ---------------- K4: fused layer-b + fc1, fully packed f32x2, f16 output ----------------
__global__ __launch_bounds__(256)
void k_vertex(const float* __restrict__ w0b, const float* __restrict__ b0b,
              const float* __restrict__ w1b, const float* __restrict__ b1b,
              const float* __restrict__ fc1w, const float* __restrict__ fc1b) {
    __shared__ u64t s_w0d[100], s_w1d[100], s_b0d[20], s_b1d[20], s_f1d[200];
    __shared__ float s_f1b[16];
    int tid = threadIdx.x;
    if (tid < 100) { float a = w0b[tid], b = w1b[tid]; s_w0d[tid] = pk2(a, a); s_w1d[tid] = pk2(b, b); }
    if (tid < 20)  { float a = b0b[tid], b = b1b[tid]; s_b0d[tid] = pk2(a, a); s_b1d[tid] = pk2(b, b); }
    if (tid < 200) { float f = fc1w[tid]; s_f1d[tid] = pk2(f, f); }
    if (tid < 10)  s_f1b[tid] = fc1b[tid];
    __syncthreads();

    int base = (blockIdx.x * blockDim.x + threadIdx.x) * 4;
    if (base >= V_TOTAL) return;   // V_TOTAL % 4 == 0

    // Load 4 vertices, transpose into packed vertex-pairs
    float x1[4][5], sb[4][5], deg[4];
#pragma unroll
    for (int u = 0; u < 4; u++) {
        int v = base + u;
        uint4 xr = g_x1h[v];
        float2 f;
        f = u2f2(xr.x); x1[u][0] = f.x; x1[u][1] = f.y;
        f = u2f2(xr.y); x1[u][2] = f.x; x1[u][3] = f.y;
        f = u2f2(xr.z); x1[u][4] = f.x; deg[u] = f.y;
        uint4 srr = g_sbh[v];
        f = u2f2(srr.x); sb[u][0] = f.x; sb[u][1] = f.y;
        f = u2f2(srr.y); sb[u][2] = f.x; sb[u][3] = f.y;
        f = u2f2(srr.z); sb[u][4] = f.x;
    }
    u64t x1p[2][5], sbp[2][5], degp[2];
#pragma unroll
    for (int m = 0; m < 5; m++) {
        x1p[0][m] = pk2(x1[0][m], x1[1][m]); x1p[1][m] = pk2(x1[2][m], x1[3][m]);
        sbp[0][m] = pk2(sb[0][m], sb[1][m]); sbp[1][m] = pk2(sb[2][m], sb[3][m]);
    }
    degp[0] = pk2(deg[0], deg[1]); degp[1] = pk2(deg[2], deg[3]);

    u64t yac[10][2];
#pragma unroll
    for (int q = 0; q < 10; q++) {
        float bq = s_f1b[q];
        yac[q][0] = pk2(bq, bq);
        yac[q][1] = pk2(bq, bq);
    }

#pragma unroll
    for (int n = 0; n < 20; n++) {
        u64t t0 = s_b0d[n], t1 = t0;
        u64t b1d = s_b1d[n];
        fma2(t0, degp[0], b1d);
        fma2(t1, degp[1], b1d);
#pragma unroll
        for (int m = 0; m < 5; m++) {
            u64t w0 = s_w0d[5 * n + m], w1 = s_w1d[5 * n + m];
            fma2(t0, x1p[0][m], w0); fma2(t0, sbp[0][m], w1);
            fma2(t1, x1p[1][m], w0); fma2(t1, sbp[1][m], w1);
        }
        float a, b, c, d;
        upk2(t0, a, b); upk2(t1, c, d);
        u64t xp0 = pk2(leaky(a), leaky(b));
        u64t xp1 = pk2(leaky(c), leaky(d));
#pragma unroll
        for (int q = 0; q < 10; q++) {
            u64t fw2 = s_f1d[20 * q + n];
            fma2(yac[q][0], xp0, fw2);
            fma2(yac[q][1], xp1, fw2);
        }
    }

    // leaky + convert to f16 pairs along flattened (vert,q) index
    float yf[40];
#pragma unroll
    for (int q = 0; q < 10; q++) {
        float a, b;
        upk2(yac[q][0], a, b); yf[q] = leaky(a); yf[10 + q] = leaky(b);
        upk2(yac[q][1], a, b); yf[20 + q] = leaky(a); yf[30 + q] = leaky(b);
    }
    unsigned yo2[20];
#pragma unroll
    for (int t = 0; t < 20; t++) yo2[t] = h2u(__floats2half2_rn(yf[2 * t], yf[2 * t + 1]));
    uint4* dst = (uint4*)(g_yh2 + (size_t)base * 5);   // base%4==0 -> 16B aligned
#pragma unroll
    for (int t = 0; t < 5; t++)
        dst[t] = make_uint4(yo2[4 * t], yo2[4 * t + 1], yo2[4 * t + 2], yo2[4 * t + 3]);
}

// ---------------- K5: fc2 split-K GEMM, f16 y, 32-k tiles, packed f32x2 ----------------
#define KSPLIT 153
#define KCHUNK 384    /* multiple of 32; 153*384 = 58752 >= 58500 */
__global__ __launch_bounds__(256)
void k_fc2(const float* __restrict__ w2) {
    __shared__ float ys[32][68];     // [k][batch-row]
    __shared__ u64t  ws2[32][64];    // [k][out-col], duplicated (w,w)
    int m0 = blockIdx.x * 64;
    int ks = blockIdx.y * KCHUNK;
    int ke = min(ks + KCHUNK, K2DIM);
    int tid = threadIdx.x;
    int row = tid >> 2, kq = tid & 3;     // loader: 8 k-values per thread
    int tr = tid & 15, tc = tid >> 4;     // compute: 4 batch x 4 out
    u64t acc[4][2];
    u64t z = pk2(0.f, 0.f);
#pragma unroll
    for (int o = 0; o < 4; o++) { acc[o][0] = z; acc[o][1] = z; }

    const unsigned* ybase = g_yh2 + (size_t)(m0 + row) * (K2DIM / 2);
    const float*    wbase = w2 + (size_t)row * K2DIM;

    for (int k0 = ks; k0 < ke; k0 += 32) {
        int kA = k0 + kq * 8;
        float yfv[8], wfv[8];
#pragma unroll
        for (int h = 0; h < 2; h++) {
            int k = kA + h * 4;
            uint2 u = make_uint2(0u, 0u);
            float4 wv = make_float4(0.f, 0.f, 0.f, 0.f);
            if (k + 4 <= ke) {   // ke % 4 == 0
                u  = *(const uint2*)(ybase + (k >> 1));
                wv = __ldg((const float4*)(wbase + k));
            }
            float2 f0 = u2f2(u.x), f1 = u2f2(u.y);
            yfv[h * 4 + 0] = f0.x; yfv[h * 4 + 1] = f0.y;
            yfv[h * 4 + 2] = f1.x; yfv[h * 4 + 3] = f1.y;
            wfv[h * 4 + 0] = wv.x; wfv[h * 4 + 1] = wv.y;
            wfv[h * 4 + 2] = wv.z; wfv[h * 4 + 3] = wv.w;
        }
        __syncthreads();
#pragma unroll
        for (int j = 0; j < 8; j++) {
            ys[kq * 8 + j][row] = yfv[j];
            ws2[kq * 8 + j][row] = pk2(wfv[j], wfv[j]);
        }
        __syncthreads();
#pragma unroll
        for (int kk = 0; kk < 32; kk++) {
            ulonglong2 yp = *(const ulonglong2*)&ys[kk][tr * 4];
#pragma unroll
            for (int o = 0; o < 4; o++) {
                u64t w = ws2[kk][tc * 4 + o];
                fma2(acc[o][0], yp.x, w);
                fma2(acc[o][1], yp.y, w);
            }
        }
    }
#pragma unroll
    for (int o = 0; o < 4; o++) {
        float a, b;
        upk2(acc[o][0], a, b);
        atomicAdd(&g_acc[(m0 + tr * 4 + 0) * NOUT + tc * 4 + o], a);
        atomicAdd(&g_acc[(m0 + tr * 4 + 1) * NOUT + tc * 4 + o], b);
        upk2(acc[o][1], a, b);
        atomicAdd(&g_acc[(m0 + tr * 4 + 2) * NOUT + tc * 4 + o], a);
        atomicAdd(&g_acc[(m0 + tr * 4 + 3) * NOUT + tc * 4 + o], b);
    }
}

// ---------------- K6: bias + softmax ----------------
__global__ void k_softmax(const float* __restrict__ fc2b, float* __restrict__ out) {
    int b = blockIdx.x * 8 + (threadIdx.x >> 5);
    int lane = threadIdx.x & 31;
    if (b >= BATCH) return;
    float v0 = g_acc[b * 64 + lane]      + __ldg(fc2b + lane);
    float v1 = g_acc[b * 64 + 32 + lane] + __ldg(fc2b + 32 + lane);
    float m = fmaxf(v0, v1);
#pragma unroll
    for (int o = 16; o; o >>= 1) m = fmaxf(m, __shfl_xor_sync(0xffffffffu, m, o));
    float e0 = expf(v0 - m), e1 = expf(v1 - m);
    float s = e0 + e1;
#pragma unroll
    for (int o = 16; o; o >>= 1) s += __shfl_xor_sync(0xffffffffu, s, o);
    float inv = 1.f / s;
    out[b * 64 + lane]      = e0 * inv;
    out[b * 64 + 32 + lane] = e1 * inv;
}

// ---------------- launch ----------------
extern "C" void kernel_launch(void* const* d_in, const int* in_sizes, int n_in,
                              void* d_out, int out_size) {
    const float* verts = (const float*)d_in[0];
    const int2*  edges = (const int2*)d_in[1];
    const float* w0a  = (const float*)d_in[2];
    const float* b0a  = (const float*)d_in[3];
    const float* w1a  = (const float*)d_in[4];
    const float* b1a  = (const float*)d_in[5];
    const float* w0b  = (const float*)d_in[6];
    const float* b0b  = (const float*)d_in[7];
    const float* w1b  = (const float*)d_in[8];
    const float* b1b  = (const float*)d_in[9];
    const float* fc1w = (const float*)d_in[10];
    const float* fc1b = (const float*)d_in[11];
    const float* fc2w = (const float*)d_in[12];
    const float* fc2b = (const float*)d_in[13];

    k_prep<<<4096, 256>>>(verts);
    k_scatter_a<<<(E_TOTAL + 255) / 256, 256>>>(edges);
    k_x1<<<(V_TOTAL + 255) / 256, 256>>>(verts, w0a, b0a, w1a, b1a);
    k_scatter_b<<<(E_TOTAL + 255) / 256, 256>>>(edges);
    k_vertex<<<(V_TOTAL / 4 + 255) / 256, 256>>>(w0b, b0b, w1b, b1b, fc1w, fc1b);
    k_fc2<<<dim3(4, KSPLIT), 256>>>(fc2w);
    k_softmax<<<32, 256>>>(fc2b, (float*)d_out);
}

// round 7
// speedup vs baseline: 1.4184x; 1.0074x over previous
#include <cuda_runtime.h>
#include <cuda_fp16.h>
#include <cstdint>

#define V_TOTAL 1497600
#define E_TOTAL 4492800
#define BATCH   256
#define VPM     5850
#define K2DIM   58500   /* VPM*10 */
#define NOUT    64
#define NEG     0.01f

// ---------------- scratch ----------------
__device__ uint2  g_vph[V_TOTAL];           // verts f16: {h2(x,y), h2(z,1)}
__device__ uint2  g_sah[V_TOTAL];           // layer-a sums f16: {h2(sx,sy), h2(sz,deg)}
__device__ uint4  g_x1h[V_TOTAL];           // x1 f16: {x0,x1},{x2,x3},{x4,deg},{0,0}
__device__ uint4  g_sbh[V_TOTAL];           // layer-b sums f16, same packing
__device__ unsigned g_yh2[V_TOTAL * 5];     // fc1 output f16, h2 pairs along k
__device__ float  g_acc[BATCH * NOUT];      // fc2 split-K accumulator

// ---------------- helpers ----------------
__device__ __forceinline__ void red_add_h8(uint4* addr, uint4 v) {
    asm volatile("red.global.add.noftz.v4.f16x2 [%0], {%1,%2,%3,%4};"
                 :: "l"(addr), "r"(v.x), "r"(v.y), "r"(v.z), "r"(v.w) : "memory");
}
__device__ __forceinline__ void red_add_h4(uint2* addr, uint2 v) {
    asm volatile("red.global.add.noftz.v2.f16x2 [%0], {%1,%2};"
                 :: "l"(addr), "r"(v.x), "r"(v.y) : "memory");
}
__device__ __forceinline__ float leaky(float t) { return t >= 0.f ? t : NEG * t; }

typedef unsigned long long u64t;
__device__ __forceinline__ u64t pk2(float a, float b) {
    u64t r; asm("mov.b64 %0,{%1,%2};" : "=l"(r) : "f"(a), "f"(b)); return r;
}
__device__ __forceinline__ void fma2(u64t& a, u64t x, u64t y) {
    asm("fma.rn.f32x2 %0,%1,%2,%0;" : "+l"(a) : "l"(x), "l"(y));
}
__device__ __forceinline__ void upk2(u64t d, float& a, float& b) {
    asm("mov.b64 {%0,%1},%2;" : "=f"(a), "=f"(b) : "l"(d));
}
__device__ __forceinline__ unsigned h2u(__half2 h) { return *reinterpret_cast<unsigned*>(&h); }
__device__ __forceinline__ float2 u2f2(unsigned u) {
    __half2 h = *reinterpret_cast<__half2*>(&u);
    return __half22float2(h);
}

// ---------------- K0: build f16 verts, zero g_sah / g_acc ----------------
__global__ void k_prep(const float* __restrict__ verts) {
    int i = blockIdx.x * blockDim.x + threadIdx.x;
    int stride = gridDim.x * blockDim.x;
    for (int v = i; v < V_TOTAL; v += stride) {
        float x = verts[3 * v + 0], y = verts[3 * v + 1], z = verts[3 * v + 2];
        g_vph[v] = make_uint2(h2u(__floats2half2_rn(x, y)), h2u(__floats2half2_rn(z, 1.f)));
        g_sah[v] = make_uint2(0u, 0u);
    }
    if (i < BATCH * NOUT) g_acc[i] = 0.f;
}

// ---------------- K1: scatter verts+degree (f16, 8B rows) ----------------
__global__ void k_scatter_a(const int2* __restrict__ edges) {
    int e = blockIdx.x * blockDim.x + threadIdx.x;
    if (e >= E_TOTAL) return;
    int2 ij = __ldcs(edges + e);
    uint2 vi = __ldg(g_vph + ij.x);
    uint2 vj = __ldg(g_vph + ij.y);
    red_add_h4(g_sah + ij.x, vj);
    red_add_h4(g_sah + ij.y, vi);
}

// ---------------- K2: x1 = leaky(...) -> f16 rows; zero g_sbh ----------------
__global__ void k_x1(const float* __restrict__ verts,
                     const float* __restrict__ w0a, const float* __restrict__ b0a,
                     const float* __restrict__ w1a, const float* __restrict__ b1a) {
    int v = blockIdx.x * blockDim.x + threadIdx.x;
    if (v >= V_TOTAL) return;
    float p0 = verts[3 * v + 0], p1 = verts[3 * v + 1], p2 = verts[3 * v + 2];
    uint2 sr = g_sah[v];
    float2 sxy = u2f2(sr.x), szd = u2f2(sr.y);   // {sum_x,sum_y},{sum_z,degree}
    float o[5];
#pragma unroll
    for (int m = 0; m < 5; m++) {
        float t = __ldg(b0a + m) + szd.y * __ldg(b1a + m);
        t += p0 * __ldg(w0a + 3 * m + 0) + p1 * __ldg(w0a + 3 * m + 1) + p2 * __ldg(w0a + 3 * m + 2);
        t += sxy.x * __ldg(w1a + 3 * m + 0) + sxy.y * __ldg(w1a + 3 * m + 1) + szd.x * __ldg(w1a + 3 * m + 2);
        o[m] = leaky(t);
    }
    uint4 row;
    row.x = h2u(__floats2half2_rn(o[0], o[1]));
    row.y = h2u(__floats2half2_rn(o[2], o[3]));
    row.z = h2u(__floats2half2_rn(o[4], szd.y));   // degree rides along (exact in f16)
    row.w = 0u;
    g_x1h[v] = row;
    g_sbh[v] = make_uint4(0u, 0u, 0u, 0u);
}

// ---------------- K3: scatter x1 (f16, 16B rows) ----------------
__global__ void k_scatter_b(const int2* __restrict__ edges) {
    int e = blockIdx.x * blockDim.x + threadIdx.x;
    if (e >= E_TOTAL) return;
    int2 ij = __ldcs(edges + e);
    uint4 xi = __ldg(g_x1h + ij.x);
    uint4 xj = __ldg(g_x1h + ij.y);
    red_add_h8(g_sbh + ij.x, xj);
    red_add_h8(g_sbh + ij.y, xi);
}

// ---------------- K4: fused layer-b + fc1, fully packed f32x2, f16 output ----------------
__global__ __launch_bounds__(256)
void k_vertex(const float* __restrict__ w0b, const float* __restrict__ b0b,
              const float* __restrict__ w1b, const float* __restrict__ b1b,
              const float* __restrict__ fc1w, const float* __restrict__ fc1b) {
    __shared__ u64t s_w0d[100], s_w1d[100], s_b0d[20], s_b1d[20], s_f1d[200];
    __shared__ float s_f1b[16];
    int tid = threadIdx.x;
    if (tid < 100) { float a = w0b[tid], b = w1b[tid]; s_w0d[tid] = pk2(a, a); s_w1d[tid] = pk2(b, b); }
    if (tid < 20)  { float a = b0b[tid], b = b1b[tid]; s_b0d[tid] = pk2(a, a); s_b1d[tid] = pk2(b, b); }
    if (tid < 200) { float f = fc1w[tid]; s_f1d[tid] = pk2(f, f); }
    if (tid < 10)  s_f1b[tid] = fc1b[tid];
    __syncthreads();

    int base = (blockIdx.x * blockDim.x + threadIdx.x) * 4;
    if (base >= V_TOTAL) return;   // V_TOTAL % 4 == 0

    // Load 4 vertices, transpose into packed vertex-pairs
    float x1[4][5], sb[4][5], deg[4];
#pragma unroll
    for (int u = 0; u < 4; u++) {
        int v = base + u;
        uint4 xr = g_x1h[v];
        float2 f;
        f = u2f2(xr.x); x1[u][0] = f.x; x1[u][1] = f.y;
        f = u2f2(xr.y); x1[u][2] = f.x; x1[u][3] = f.y;
        f = u2f2(xr.z); x1[u][4] = f.x; deg[u] = f.y;
        uint4 srr = g_sbh[v];
        f = u2f2(srr.x); sb[u][0] = f.x; sb[u][1] = f.y;
        f = u2f2(srr.y); sb[u][2] = f.x; sb[u][3] = f.y;
        f = u2f2(srr.z); sb[u][4] = f.x;
    }
    u64t x1p[2][5], sbp[2][5], degp[2];
#pragma unroll
    for (int m = 0; m < 5; m++) {
        x1p[0][m] = pk2(x1[0][m], x1[1][m]); x1p[1][m] = pk2(x1[2][m], x1[3][m]);
        sbp[0][m] = pk2(sb[0][m], sb[1][m]); sbp[1][m] = pk2(sb[2][m], sb[3][m]);
    }
    degp[0] = pk2(deg[0], deg[1]); degp[1] = pk2(deg[2], deg[3]);

    u64t yac[10][2];
#pragma unroll
    for (int q = 0; q < 10; q++) {
        float bq = s_f1b[q];
        yac[q][0] = pk2(bq, bq);
        yac[q][1] = pk2(bq, bq);
    }

#pragma unroll
    for (int n = 0; n < 20; n++) {
        u64t t0 = s_b0d[n], t1 = t0;
        u64t b1d = s_b1d[n];
        fma2(t0, degp[0], b1d);
        fma2(t1, degp[1], b1d);
#pragma unroll
        for (int m = 0; m < 5; m++) {
            u64t w0 = s_w0d[5 * n + m], w1 = s_w1d[5 * n + m];
            fma2(t0, x1p[0][m], w0); fma2(t0, sbp[0][m], w1);
            fma2(t1, x1p[1][m], w0); fma2(t1, sbp[1][m], w1);
        }
        float a, b, c, d;
        upk2(t0, a, b); upk2(t1, c, d);
        u64t xp0 = pk2(leaky(a), leaky(b));
        u64t xp1 = pk2(leaky(c), leaky(d));
#pragma unroll
        for (int q = 0; q < 10; q++) {
            u64t fw2 = s_f1d[20 * q + n];
            fma2(yac[q][0], xp0, fw2);
            fma2(yac[q][1], xp1, fw2);
        }
    }

    // leaky + convert to f16 pairs along flattened (vert,q) index
    float yf[40];
#pragma unroll
    for (int q = 0; q < 10; q++) {
        float a, b;
        upk2(yac[q][0], a, b); yf[q] = leaky(a); yf[10 + q] = leaky(b);
        upk2(yac[q][1], a, b); yf[20 + q] = leaky(a); yf[30 + q] = leaky(b);
    }
    unsigned yo2[20];
#pragma unroll
    for (int t = 0; t < 20; t++) yo2[t] = h2u(__floats2half2_rn(yf[2 * t], yf[2 * t + 1]));
    uint4* dst = (uint4*)(g_yh2 + (size_t)base * 5);   // base%4==0 -> 16B aligned
#pragma unroll
    for (int t = 0; t < 5; t++)
        dst[t] = make_uint4(yo2[4 * t], yo2[4 * t + 1], yo2[4 * t + 2], yo2[4 * t + 3]);
}

// ---------------- K5: fc2 split-K GEMM, f16 y, 32-k tiles, packed f32x2 ----------------
#define KSPLIT 153
#define KCHUNK 384    /* multiple of 32; 153*384 = 58752 >= 58500 */
__global__ __launch_bounds__(256)
void k_fc2(const float* __restrict__ w2) {
    __shared__ float ys[32][68];     // [k][batch-row]
    __shared__ u64t  ws2[32][64];    // [k][out-col], duplicated (w,w)
    int m0 = blockIdx.x * 64;
    int ks = blockIdx.y * KCHUNK;
    int ke = min(ks + KCHUNK, K2DIM);
    int tid = threadIdx.x;
    int row = tid >> 2, kq = tid & 3;     // loader: 8 k-values per thread
    int tr = tid & 15, tc = tid >> 4;     // compute: 4 batch x 4 out
    u64t acc[4][2];
    u64t z = pk2(0.f, 0.f);
#pragma unroll
    for (int o = 0; o < 4; o++) { acc[o][0] = z; acc[o][1] = z; }

    const unsigned* ybase = g_yh2 + (size_t)(m0 + row) * (K2DIM / 2);
    const float*    wbase = w2 + (size_t)row * K2DIM;

    for (int k0 = ks; k0 < ke; k0 += 32) {
        int kA = k0 + kq * 8;
        float yfv[8], wfv[8];
#pragma unroll
        for (int h = 0; h < 2; h++) {
            int k = kA + h * 4;
            uint2 u = make_uint2(0u, 0u);
            float4 wv = make_float4(0.f, 0.f, 0.f, 0.f);
            if (k + 4 <= ke) {   // ke % 4 == 0
                u  = *(const uint2*)(ybase + (k >> 1));
                wv = __ldg((const float4*)(wbase + k));
            }
            float2 f0 = u2f2(u.x), f1 = u2f2(u.y);
            yfv[h * 4 + 0] = f0.x; yfv[h * 4 + 1] = f0.y;
            yfv[h * 4 + 2] = f1.x; yfv[h * 4 + 3] = f1.y;
            wfv[h * 4 + 0] = wv.x; wfv[h * 4 + 1] = wv.y;
            wfv[h * 4 + 2] = wv.z; wfv[h * 4 + 3] = wv.w;
        }
        __syncthreads();
#pragma unroll
        for (int j = 0; j < 8; j++) {
            ys[kq * 8 + j][row] = yfv[j];
            ws2[kq * 8 + j][row] = pk2(wfv[j], wfv[j]);
        }
        __syncthreads();
#pragma unroll
        for (int kk = 0; kk < 32; kk++) {
            ulonglong2 yp = *(const ulonglong2*)&ys[kk][tr * 4];
#pragma unroll
            for (int o = 0; o < 4; o++) {
                u64t w = ws2[kk][tc * 4 + o];
                fma2(acc[o][0], yp.x, w);
                fma2(acc[o][1], yp.y, w);
            }
        }
    }
#pragma unroll
    for (int o = 0; o < 4; o++) {
        float a, b;
        upk2(acc[o][0], a, b);
        atomicAdd(&g_acc[(m0 + tr * 4 + 0) * NOUT + tc * 4 + o], a);
        atomicAdd(&g_acc[(m0 + tr * 4 + 1) * NOUT + tc * 4 + o], b);
        upk2(acc[o][1], a, b);
        atomicAdd(&g_acc[(m0 + tr * 4 + 2) * NOUT + tc * 4 + o], a);
        atomicAdd(&g_acc[(m0 + tr * 4 + 3) * NOUT + tc * 4 + o], b);
    }
}

// ---------------- K6: bias + softmax ----------------
__global__ void k_softmax(const float* __restrict__ fc2b, float* __restrict__ out) {
    int b = blockIdx.x * 8 + (threadIdx.x >> 5);
    int lane = threadIdx.x & 31;
    if (b >= BATCH) return;
    float v0 = g_acc[b * 64 + lane]      + __ldg(fc2b + lane);
    float v1 = g_acc[b * 64 + 32 + lane] + __ldg(fc2b + 32 + lane);
    float m = fmaxf(v0, v1);
#pragma unroll
    for (int o = 16; o; o >>= 1) m = fmaxf(m, __shfl_xor_sync(0xffffffffu, m, o));
    float e0 = expf(v0 - m), e1 = expf(v1 - m);
    float s = e0 + e1;
#pragma unroll
    for (int o = 16; o; o >>= 1) s += __shfl_xor_sync(0xffffffffu, s, o);
    float inv = 1.f / s;
    out[b * 64 + lane]      = e0 * inv;
    out[b * 64 + 32 + lane] = e1 * inv;
}

// ---------------- launch ----------------
extern "C" void kernel_launch(void* const* d_in, const int* in_sizes, int n_in,
                              void* d_out, int out_size) {
    const float* verts = (const float*)d_in[0];
    const int2*  edges = (const int2*)d_in[1];
    const float* w0a  = (const float*)d_in[2];
    const float* b0a  = (const float*)d_in[3];
    const float* w1a  = (const float*)d_in[4];
    const float* b1a  = (const float*)d_in[5];
    const float* w0b  = (const float*)d_in[6];
    const float* b0b  = (const float*)d_in[7];
    const float* w1b  = (const float*)d_in[8];
    const float* b1b  = (const float*)d_in[9];
    const float* fc1w = (const float*)d_in[10];
    const float* fc1b = (const float*)d_in[11];
    const float* fc2w = (const float*)d_in[12];
    const float* fc2b = (const float*)d_in[13];

    k_prep<<<4096, 256>>>(verts);
    k_scatter_a<<<(E_TOTAL + 255) / 256, 256>>>(edges);
    k_x1<<<(V_TOTAL + 255) / 256, 256>>>(verts, w0a, b0a, w1a, b1a);
    k_scatter_b<<<(E_TOTAL + 255) / 256, 256>>>(edges);
    k_vertex<<<(V_TOTAL / 4 + 255) / 256, 256>>>(w0b, b0b, w1b, b1b, fc1w, fc1b);
    k_fc2<<<dim3(4, KSPLIT), 256>>>(fc2w);
    k_softmax<<<32, 256>>>(fc2b, (float*)d_out);
}